// round 3
// baseline (speedup 1.0000x reference)
#include <cuda_runtime.h>

#define B_   8
#define C_   256
#define N_   4096
#define CQK_ 32

// ---------------- scratch (static device globals; no allocations) ----------------
__device__ float g_q[(size_t)B_ * CQK_ * N_];   // [b][o][n]
__device__ float g_k[(size_t)B_ * CQK_ * N_];   // [b][o][n]
__device__ float g_v[(size_t)B_ * C_ * N_];     // [b][c][n]
__device__ float g_y[(size_t)B_ * C_ * N_];     // pre-BN residual output
__device__ float g_mean[C_];
__device__ float g_istd[C_];

// ---------------- packed f32x2 helpers (Blackwell FFMA2) ----------------
__device__ __forceinline__ unsigned long long pack2(float v) {
    unsigned long long r;
    asm("mov.b64 %0, {%1, %1};" : "=l"(r) : "f"(v));
    return r;
}
__device__ __forceinline__ void ffma2(unsigned long long& d, unsigned long long a, unsigned long long b) {
    asm("fma.rn.f32x2 %0, %1, %2, %0;" : "+l"(d) : "l"(a), "l"(b));
}
__device__ __forceinline__ void mul2(unsigned long long& d, unsigned long long a) {
    asm("mul.rn.f32x2 %0, %0, %1;" : "+l"(d) : "l"(a));
}
__device__ __forceinline__ float2 unpack2(unsigned long long v) {
    float2 r;
    asm("mov.b64 {%0, %1}, %2;" : "=f"(r.x), "=f"(r.y) : "l"(v));
    return r;
}

// ---------------- projection GEMM: out[b][o][n] = sum_c W[o][c] x[b][c][n] + bias[o] ----------------
template<int OTILE, int SEL>
__global__ __launch_bounds__(256) void proj_kernel(const float* __restrict__ x,
                                                   const float* __restrict__ W,
                                                   const float* __restrict__ bias,
                                                   int Ototal) {
    float* out = (SEL == 0) ? g_q : (SEL == 1) ? g_k : g_v;
    const int n  = blockIdx.x * 256 + threadIdx.x;
    const int o0 = blockIdx.y * OTILE;
    const int bb = blockIdx.z;
    __shared__ float Ws[OTILE * 64];
    float acc[OTILE];
#pragma unroll
    for (int o = 0; o < OTILE; o++) acc[o] = 0.f;
    const float* xb = x + (size_t)bb * C_ * N_;
#pragma unroll 1
    for (int c0 = 0; c0 < C_; c0 += 64) {
        __syncthreads();
        for (int idx = threadIdx.x; idx < OTILE * 64; idx += 256) {
            int oo = idx >> 6, cc = idx & 63;
            Ws[idx] = W[(o0 + oo) * C_ + c0 + cc];
        }
        __syncthreads();
#pragma unroll 8
        for (int cc = 0; cc < 64; cc++) {
            float xv = xb[(c0 + cc) * N_ + n];
#pragma unroll
            for (int o = 0; o < OTILE; o++) acc[o] = fmaf(Ws[o * 64 + cc], xv, acc[o]);
        }
    }
    float* ob = out + (size_t)bb * Ototal * N_;
#pragma unroll
    for (int o = 0; o < OTILE; o++) ob[(o0 + o) * N_ + n] = acc[o] + bias[o0 + o];
}

// ---------------- flash attention (fp32, FFMA2 PV mainloop) ----------------
// grid: (N/64, B), block 256. thread t: query i = t>>2 (0..63), group g = t&3.
// Per thread: 64 output channels c = c4*16 + g*4 + e  (c4 0..15, e 0..3), held as 32 f32x2 pairs.
#define QS_STRIDE 33
#define KS_STRIDE 64
#define PS_STRIDE 65
#define VS_STRIDE 260
constexpr int SMEM_Q = 64 * QS_STRIDE;
constexpr int SMEM_K = 32 * KS_STRIDE;
constexpr int SMEM_P = 64 * PS_STRIDE;
constexpr int SMEM_V = 64 * VS_STRIDE;
constexpr int SMEM_ATT_BYTES = (SMEM_Q + SMEM_K + SMEM_P + SMEM_V) * 4;   // 99840 B

__global__ __launch_bounds__(256, 2) void attn_kernel(const float* __restrict__ x,
                                                      const float* __restrict__ gamma) {
    extern __shared__ float sm[];
    float* Qs = sm;
    float* Ks = Qs + SMEM_Q;
    float* Ps = Ks + SMEM_K;
    float* Vs = Ps + SMEM_P;

    const int t  = threadIdx.x;
    const int i  = t >> 2;
    const int g  = t & 3;
    const int n0 = blockIdx.x * 64;
    const int bb = blockIdx.y;

    const float* qb = g_q + (size_t)bb * CQK_ * N_;
    const float* kb = g_k + (size_t)bb * CQK_ * N_;
    const float* vb = g_v + (size_t)bb * C_ * N_;

    // Q tile: Qs[i][o] <- q[b][o][n0+i]
    for (int idx = t; idx < 64 * 32; idx += 256) {
        int o = idx >> 6, ii = idx & 63;
        Qs[ii * QS_STRIDE + o] = qb[o * N_ + n0 + ii];
    }

    unsigned long long O2[32];
#pragma unroll
    for (int p = 0; p < 32; p++) O2[p] = 0ull;
    float mrow = -1e30f, lrow = 0.f;

    const int kr_o  = t >> 3;        // K loader: row o (0..31)
    const int kr_j  = (t & 7) * 8;   // K loader: j offset
    const int vr_c  = t >> 3;        // V loader: c row within pass (0..31)
    const int vr_jq = t & 7;         // V loader: j-octet

#pragma unroll 1
    for (int kt = 0; kt < 64; kt++) {
        const int j0 = kt * 64;
        __syncthreads();   // previous tile's PV reads done -> safe to overwrite Ks/Vs
        // ---- K tile: Ks[o][j] <- k[b][o][j0+j]
        {
            const float* src = &kb[kr_o * N_ + j0 + kr_j];
            float4 a  = *(const float4*)src;
            float4 b4 = *(const float4*)(src + 4);
            *(float4*)&Ks[kr_o * KS_STRIDE + kr_j]     = a;
            *(float4*)&Ks[kr_o * KS_STRIDE + kr_j + 4] = b4;
        }
        // ---- V tile, transposed + XOR-swizzled: Vs[j][c ^ ((j>>3)*4)] <- v[b][c][j0+j]
        {
            const int sw = vr_jq * 4;   // swizzle for this thread's 8 js (all share j>>3)
#pragma unroll
            for (int pass = 0; pass < 8; pass++) {
                int c = pass * 32 + vr_c;
                const float* src = &vb[(size_t)c * N_ + j0 + vr_jq * 8];
                float4 a  = *(const float4*)src;
                float4 b4 = *(const float4*)(src + 4);
                float* dst = &Vs[(vr_jq * 8) * VS_STRIDE + (c ^ sw)];
                dst[0 * VS_STRIDE] = a.x;  dst[1 * VS_STRIDE] = a.y;
                dst[2 * VS_STRIDE] = a.z;  dst[3 * VS_STRIDE] = a.w;
                dst[4 * VS_STRIDE] = b4.x; dst[5 * VS_STRIDE] = b4.y;
                dst[6 * VS_STRIDE] = b4.z; dst[7 * VS_STRIDE] = b4.w;
            }
        }
        __syncthreads();

        // ---- S[i][j] for this thread's 16 js: j = q4*16 + g*4 + e
        float S[16];
#pragma unroll
        for (int q = 0; q < 16; q++) S[q] = 0.f;
#pragma unroll
        for (int o = 0; o < 32; o++) {
            float qv = Qs[i * QS_STRIDE + o];
#pragma unroll
            for (int q4 = 0; q4 < 4; q4++) {
                float4 kv = *(const float4*)&Ks[o * KS_STRIDE + q4 * 16 + g * 4];
                S[q4 * 4 + 0] = fmaf(qv, kv.x, S[q4 * 4 + 0]);
                S[q4 * 4 + 1] = fmaf(qv, kv.y, S[q4 * 4 + 1]);
                S[q4 * 4 + 2] = fmaf(qv, kv.z, S[q4 * 4 + 2]);
                S[q4 * 4 + 3] = fmaf(qv, kv.w, S[q4 * 4 + 3]);
            }
        }
        // ---- online softmax across the 4-lane query group
        float tmax = S[0];
#pragma unroll
        for (int q = 1; q < 16; q++) tmax = fmaxf(tmax, S[q]);
        tmax = fmaxf(tmax, __shfl_xor_sync(0xffffffffu, tmax, 1));
        tmax = fmaxf(tmax, __shfl_xor_sync(0xffffffffu, tmax, 2));
        float mnew  = fmaxf(mrow, tmax);
        float alpha = __expf(mrow - mnew);
        float psum = 0.f;
        float P[16];
#pragma unroll
        for (int q = 0; q < 16; q++) { P[q] = __expf(S[q] - mnew); psum += P[q]; }
        psum += __shfl_xor_sync(0xffffffffu, psum, 1);
        psum += __shfl_xor_sync(0xffffffffu, psum, 2);
        lrow = lrow * alpha + psum;
        mrow = mnew;
#pragma unroll
        for (int q4 = 0; q4 < 4; q4++)
#pragma unroll
            for (int e = 0; e < 4; e++)
                Ps[i * PS_STRIDE + q4 * 16 + g * 4 + e] = P[q4 * 4 + e];
        unsigned long long av = pack2(alpha);
#pragma unroll
        for (int p = 0; p < 32; p++) mul2(O2[p], av);
        __syncthreads();   // all P visible before PV

        // ---- PV: O[i][c] += sum_j P[i][j] * V[c][j]   (f32x2, swizzle-aware)
#pragma unroll 1
        for (int jq = 0; jq < 8; jq++) {
            const int sj = jq * 4;
            const float* vbase = &Vs[(jq * 8) * VS_STRIDE + ((g * 4) ^ (sj & 12))];
            const float* pbase = &Ps[i * PS_STRIDE + jq * 8];
            if (sj & 16) {
#pragma unroll 2
                for (int m = 0; m < 8; m++) {
                    unsigned long long pp = pack2(pbase[m]);
                    const float* vr = vbase + m * VS_STRIDE;
#pragma unroll
                    for (int c4 = 0; c4 < 16; c4++) {
                        ulonglong2 v2 = *(const ulonglong2*)(vr + c4 * 16);
                        const int cd = c4 ^ 1;               // swizzle bit4 -> permute accumulators
                        ffma2(O2[2 * cd],     pp, v2.x);
                        ffma2(O2[2 * cd + 1], pp, v2.y);
                    }
                }
            } else {
#pragma unroll 2
                for (int m = 0; m < 8; m++) {
                    unsigned long long pp = pack2(pbase[m]);
                    const float* vr = vbase + m * VS_STRIDE;
#pragma unroll
                    for (int c4 = 0; c4 < 16; c4++) {
                        ulonglong2 v2 = *(const ulonglong2*)(vr + c4 * 16);
                        ffma2(O2[2 * c4],     pp, v2.x);
                        ffma2(O2[2 * c4 + 1], pp, v2.y);
                    }
                }
            }
        }
    }

    // ---- epilogue: y = gamma * (O / l) + x
    const float gm   = gamma[0];
    const float linv = 1.0f / lrow;
    const float* xb = x  + (size_t)bb * C_ * N_;
    float*       yb = g_y + (size_t)bb * C_ * N_;
    const int n = n0 + i;
#pragma unroll
    for (int c4 = 0; c4 < 16; c4++) {
#pragma unroll
        for (int h = 0; h < 2; h++) {
            float2 ov = unpack2(O2[2 * c4 + h]);
            int c = c4 * 16 + g * 4 + h * 2;
            yb[c * N_ + n]       = fmaf(gm, ov.x * linv, xb[c * N_ + n]);
            yb[(c + 1) * N_ + n] = fmaf(gm, ov.y * linv, xb[(c + 1) * N_ + n]);
        }
    }
}

// ---------------- BatchNorm (train mode, batch stats) ----------------
__global__ __launch_bounds__(256) void bn_stats_kernel() {
    const int c = blockIdx.x;
    const int t = threadIdx.x;
    float s = 0.f, sq = 0.f;
    for (int idx = t; idx < B_ * N_; idx += 256) {
        int bb = idx >> 12;
        int n  = idx & (N_ - 1);
        float v = g_y[(size_t)bb * C_ * N_ + (size_t)c * N_ + n];
        s += v; sq += v * v;
    }
#pragma unroll
    for (int off = 16; off > 0; off >>= 1) {
        s  += __shfl_down_sync(0xffffffffu, s, off);
        sq += __shfl_down_sync(0xffffffffu, sq, off);
    }
    __shared__ float rs[8], rq[8];
    if ((t & 31) == 0) { rs[t >> 5] = s; rq[t >> 5] = sq; }
    __syncthreads();
    if (t < 32) {
        s  = (t < 8) ? rs[t] : 0.f;
        sq = (t < 8) ? rq[t] : 0.f;
#pragma unroll
        for (int off = 4; off > 0; off >>= 1) {
            s  += __shfl_down_sync(0xffffffffu, s, off);
            sq += __shfl_down_sync(0xffffffffu, sq, off);
        }
        if (t == 0) {
            const float inv = 1.0f / (float)(B_ * N_);
            float mean = s * inv;
            float var  = sq * inv - mean * mean;
            g_mean[c] = mean;
            g_istd[c] = rsqrtf(var + 1e-5f);
        }
    }
}

__global__ __launch_bounds__(256) void bn_apply_kernel(const float* __restrict__ bnw,
                                                       const float* __restrict__ bnb,
                                                       float* __restrict__ out) {
    size_t idx = ((size_t)blockIdx.x * 256 + threadIdx.x) * 4;
    int c = (int)((idx >> 12) & (C_ - 1));
    float4 v = *(const float4*)&g_y[idx];
    float is = g_istd[c];
    float wv = bnw[c] * is;
    float bv = bnb[c] - g_mean[c] * wv;
    v.x = fmaxf(fmaf(v.x, wv, bv), 0.f);
    v.y = fmaxf(fmaf(v.y, wv, bv), 0.f);
    v.z = fmaxf(fmaf(v.z, wv, bv), 0.f);
    v.w = fmaxf(fmaf(v.w, wv, bv), 0.f);
    *(float4*)&out[idx] = v;
}

// ---------------- launch ----------------
extern "C" void kernel_launch(void* const* d_in, const int* in_sizes, int n_in,
                              void* d_out, int out_size) {
    const float* x     = (const float*)d_in[0];
    const float* wq    = (const float*)d_in[1];
    const float* bq    = (const float*)d_in[2];
    const float* wk    = (const float*)d_in[3];
    const float* bk    = (const float*)d_in[4];
    const float* wv    = (const float*)d_in[5];
    const float* bv    = (const float*)d_in[6];
    const float* gamma = (const float*)d_in[7];
    const float* bnw   = (const float*)d_in[8];
    const float* bnb   = (const float*)d_in[9];
    float* out = (float*)d_out;

    proj_kernel<32, 0><<<dim3(N_ / 256, 1, B_), 256>>>(x, wq, bq, CQK_);
    proj_kernel<32, 1><<<dim3(N_ / 256, 1, B_), 256>>>(x, wk, bk, CQK_);
    proj_kernel<64, 2><<<dim3(N_ / 256, 4, B_), 256>>>(x, wv, bv, C_);

    cudaFuncSetAttribute(attn_kernel, cudaFuncAttributeMaxDynamicSharedMemorySize, SMEM_ATT_BYTES);
    attn_kernel<<<dim3(N_ / 64, B_), 256, SMEM_ATT_BYTES>>>(x, gamma);

    bn_stats_kernel<<<C_, 256>>>();
    bn_apply_kernel<<<(B_ * C_ * N_) / (256 * 4), 256>>>(bnw, bnb, out);
}

// round 4
// speedup vs baseline: 2.4081x; 2.4081x over previous
#include <cuda_runtime.h>

#define B_   8
#define C_   256
#define N_   4096
#define CQK_ 32

typedef unsigned long long ull;

// ---------------- scratch (static device globals; no allocations) ----------------
__device__ float g_q[(size_t)B_ * CQK_ * N_];   // [b][o][n]
__device__ float g_k[(size_t)B_ * CQK_ * N_];   // [b][o][n]
__device__ float g_v[(size_t)B_ * C_ * N_];     // [b][c][n]
__device__ float g_y[(size_t)B_ * C_ * N_];     // pre-BN residual output
__device__ float g_mean[C_];
__device__ float g_istd[C_];

// ---------------- packed f32x2 helpers (Blackwell FFMA2) ----------------
__device__ __forceinline__ ull pack2(float v) {
    ull r;
    asm("mov.b64 %0, {%1, %1};" : "=l"(r) : "f"(v));
    return r;
}
__device__ __forceinline__ ull packpair(float a, float b) {
    ull r;
    asm("mov.b64 %0, {%1, %2};" : "=l"(r) : "f"(a), "f"(b));
    return r;
}
__device__ __forceinline__ void ffma2(ull& d, ull a, ull b) {
    asm("fma.rn.f32x2 %0, %1, %2, %0;" : "+l"(d) : "l"(a), "l"(b));
}
__device__ __forceinline__ void mul2(ull& d, ull a) {
    asm("mul.rn.f32x2 %0, %0, %1;" : "+l"(d) : "l"(a));
}
__device__ __forceinline__ float2 unpack2(ull v) {
    float2 r;
    asm("mov.b64 {%0, %1}, %2;" : "=f"(r.x), "=f"(r.y) : "l"(v));
    return r;
}

// ---------------- projection GEMM (f32x2, dup-packed weights, 4n/thread) ----------------
// out[b][o][n] = sum_c W[o][c] x[b][c][n] + bias[o]
template<int SEL>
__global__ __launch_bounds__(256) void proj2_kernel(const float* __restrict__ x,
                                                    const float* __restrict__ W,
                                                    const float* __restrict__ bias,
                                                    int Ototal) {
    constexpr int OT = 16;
    float* out = (SEL == 0) ? g_q : (SEL == 1) ? g_k : g_v;
    const int n  = blockIdx.x * 1024 + threadIdx.x * 4;
    const int o0 = blockIdx.y * OT;
    const int bb = blockIdx.z;
    __shared__ ull Ws2[OT * 64];
    ull acc[OT][2];
#pragma unroll
    for (int o = 0; o < OT; o++) { acc[o][0] = 0ull; acc[o][1] = 0ull; }
    const float* xb = x + (size_t)bb * C_ * N_;
#pragma unroll 1
    for (int c0 = 0; c0 < C_; c0 += 64) {
        __syncthreads();
        for (int idx = threadIdx.x; idx < OT * 64; idx += 256) {
            int oo = idx >> 6, cc = idx & 63;
            Ws2[idx] = pack2(W[(o0 + oo) * C_ + c0 + cc]);
        }
        __syncthreads();
#pragma unroll 4
        for (int cc = 0; cc < 64; cc++) {
            float4 xv = *(const float4*)&xb[(size_t)(c0 + cc) * N_ + n];
            ull x01 = packpair(xv.x, xv.y);
            ull x23 = packpair(xv.z, xv.w);
#pragma unroll
            for (int o = 0; o < OT; o++) {
                ull w2 = Ws2[o * 64 + cc];
                ffma2(acc[o][0], w2, x01);
                ffma2(acc[o][1], w2, x23);
            }
        }
    }
    float* ob = out + (size_t)bb * Ototal * N_;
#pragma unroll
    for (int o = 0; o < OT; o++) {
        float bo = bias[o0 + o];
        float2 a = unpack2(acc[o][0]);
        float2 b = unpack2(acc[o][1]);
        float4 r;
        r.x = a.x + bo; r.y = a.y + bo; r.z = b.x + bo; r.w = b.y + bo;
        *(float4*)&ob[(size_t)(o0 + o) * N_ + n] = r;
    }
}

// ---------------- flash attention (fp32, register-blocked 8q x 8c per thread) ----------------
// block 256 = 8 warps. warp w: queries 8w..8w+7. lane cg (0..31): channels {4cg..4cg+3, 128+4cg..+3}.
#define QSS 68
#define KSS 64
#define PSS 68
#define VSS 260
#define OSS 69
constexpr int SMEM_Q = 32 * QSS;    // 2176
constexpr int SMEM_K = 32 * KSS;    // 2048
constexpr int SMEM_P = 64 * PSS;    // 4352
constexpr int SMEM_V = 64 * VSS;    // 16640
constexpr int SMEM_ATT_BYTES = (SMEM_Q + SMEM_K + SMEM_P + SMEM_V) * 4;   // 100864 B

__global__ __launch_bounds__(256, 2) void attn_kernel(const float* __restrict__ x,
                                                      const float* __restrict__ gamma) {
    extern __shared__ float sm[];
    float* Qs = sm;
    float* Ks = Qs + SMEM_Q;
    float* Ps = Ks + SMEM_K;
    float* Vs = Ps + SMEM_P;

    const int t  = threadIdx.x;
    const int w  = t >> 5;
    const int cg = t & 31;
    const int n0 = blockIdx.x * 64;
    const int bb = blockIdx.y;

    const float* qb = g_q + (size_t)bb * CQK_ * N_;
    const float* kb = g_k + (size_t)bb * CQK_ * N_;
    const float* vb = g_v + (size_t)bb * C_ * N_;

    // Q tile: Qs[o][i] <- q[b][o][n0+i]
    for (int idx = t; idx < 32 * 64; idx += 256) {
        int o = idx >> 6, ii = idx & 63;
        Qs[o * QSS + ii] = qb[o * N_ + n0 + ii];
    }

    ull O2[8][4];
#pragma unroll
    for (int q = 0; q < 8; q++)
#pragma unroll
        for (int u = 0; u < 4; u++) O2[q][u] = 0ull;
    float mrow[8], lrow[8];
#pragma unroll
    for (int q = 0; q < 8; q++) { mrow[q] = -1e30f; lrow[q] = 0.f; }

    const int kr_o  = t >> 3;        // K loader: row o (0..31)
    const int kr_j  = (t & 7) * 8;   // K loader: j offset
    const int vr_c  = t >> 3;        // V loader: c row within pass (0..31)
    const int vr_jq = t & 7;         // V loader: j-octet

#pragma unroll 1
    for (int kt = 0; kt < 64; kt++) {
        const int j0 = kt * 64;
        __syncthreads();   // prev PV reads of Ks/Vs/Ps done
        // ---- K tile: Ks[o][j] <- k[b][o][j0+j]
        {
            const float* src = &kb[kr_o * N_ + j0 + kr_j];
            float4 a  = *(const float4*)src;
            float4 b4 = *(const float4*)(src + 4);
            *(float4*)&Ks[kr_o * KSS + kr_j]     = a;
            *(float4*)&Ks[kr_o * KSS + kr_j + 4] = b4;
        }
        // ---- V tile, transposed + XOR-swizzled: Vs[j][c ^ ((j>>3)*4)] <- v[b][c][j0+j]
        {
            const int sw = vr_jq * 4;
#pragma unroll
            for (int pass = 0; pass < 8; pass++) {
                int c = pass * 32 + vr_c;
                const float* src = &vb[(size_t)c * N_ + j0 + vr_jq * 8];
                float4 a  = *(const float4*)src;
                float4 b4 = *(const float4*)(src + 4);
                float* dst = &Vs[(vr_jq * 8) * VSS + (c ^ sw)];
                dst[0 * VSS] = a.x;  dst[1 * VSS] = a.y;
                dst[2 * VSS] = a.z;  dst[3 * VSS] = a.w;
                dst[4 * VSS] = b4.x; dst[5 * VSS] = b4.y;
                dst[6 * VSS] = b4.z; dst[7 * VSS] = b4.w;
            }
        }
        __syncthreads();

        // ---- QK: S[8 queries][2 js] per lane; j = 2cg, 2cg+1
        ull Sj0[4], Sj1[4];
#pragma unroll
        for (int p = 0; p < 4; p++) { Sj0[p] = 0ull; Sj1[p] = 0ull; }
        {
            const float* qsw = Qs + 8 * w;
            const float* ksl = Ks + 2 * cg;
#pragma unroll 8
            for (int o = 0; o < 32; o++) {
                float2 kv = *(const float2*)(ksl + o * KSS);
                ulonglong2 qA = *(const ulonglong2*)(qsw + o * QSS);
                ulonglong2 qB = *(const ulonglong2*)(qsw + o * QSS + 4);
                ull k0 = pack2(kv.x), k1 = pack2(kv.y);
                ffma2(Sj0[0], qA.x, k0); ffma2(Sj0[1], qA.y, k0);
                ffma2(Sj0[2], qB.x, k0); ffma2(Sj0[3], qB.y, k0);
                ffma2(Sj1[0], qA.x, k1); ffma2(Sj1[1], qA.y, k1);
                ffma2(Sj1[2], qB.x, k1); ffma2(Sj1[3], qB.y, k1);
            }
        }
        float s[8][2];
#pragma unroll
        for (int p = 0; p < 4; p++) {
            float2 u0 = unpack2(Sj0[p]);
            float2 u1 = unpack2(Sj1[p]);
            s[2 * p][0]     = u0.x; s[2 * p + 1][0] = u0.y;
            s[2 * p][1]     = u1.x; s[2 * p + 1][1] = u1.y;
        }

        // ---- online softmax (row reduction across full warp)
        float P[8][2];
#pragma unroll
        for (int q = 0; q < 8; q++) {
            float rm = fmaxf(s[q][0], s[q][1]);
#pragma unroll
            for (int off = 16; off > 0; off >>= 1)
                rm = fmaxf(rm, __shfl_xor_sync(0xffffffffu, rm, off));
            float mn    = fmaxf(mrow[q], rm);
            float alpha = __expf(mrow[q] - mn);
            float e0 = __expf(s[q][0] - mn);
            float e1 = __expf(s[q][1] - mn);
            float rs = e0 + e1;
#pragma unroll
            for (int off = 16; off > 0; off >>= 1)
                rs += __shfl_xor_sync(0xffffffffu, rs, off);
            lrow[q] = lrow[q] * alpha + rs;
            mrow[q] = mn;
            P[q][0] = e0; P[q][1] = e1;
            ull av = pack2(alpha);
            mul2(O2[q][0], av); mul2(O2[q][1], av);
            mul2(O2[q][2], av); mul2(O2[q][3], av);
        }
        // ---- write P: Ps[j][i]  (lane owns js 2cg, 2cg+1; queries 8w..8w+7 consecutive)
#pragma unroll
        for (int jj = 0; jj < 2; jj++) {
            float4 pa, pb;
            pa.x = P[0][jj]; pa.y = P[1][jj]; pa.z = P[2][jj]; pa.w = P[3][jj];
            pb.x = P[4][jj]; pb.y = P[5][jj]; pb.z = P[6][jj]; pb.w = P[7][jj];
            float* d = &Ps[(2 * cg + jj) * PSS + 8 * w];
            *(float4*)d       = pa;
            *(float4*)(d + 4) = pb;
        }
        __syncthreads();

        // ---- PV: O[q][c] += P[j][q] * V[j][c]
#pragma unroll 1
        for (int jo = 0; jo < 8; jo++) {
            const float* vrow = Vs + (jo * 8) * VSS + ((cg ^ jo) << 2);
            const float* prow = Ps + (jo * 8) * PSS + 8 * w;
#pragma unroll 2
            for (int m = 0; m < 8; m++) {
                float4 pa = *(const float4*)(prow + m * PSS);
                float4 pb = *(const float4*)(prow + m * PSS + 4);
                ulonglong2 vA = *(const ulonglong2*)(vrow + m * VSS);
                ulonglong2 vB = *(const ulonglong2*)(vrow + m * VSS + 128);
                ull pp;
                pp = pack2(pa.x);
                ffma2(O2[0][0], pp, vA.x); ffma2(O2[0][1], pp, vA.y);
                ffma2(O2[0][2], pp, vB.x); ffma2(O2[0][3], pp, vB.y);
                pp = pack2(pa.y);
                ffma2(O2[1][0], pp, vA.x); ffma2(O2[1][1], pp, vA.y);
                ffma2(O2[1][2], pp, vB.x); ffma2(O2[1][3], pp, vB.y);
                pp = pack2(pa.z);
                ffma2(O2[2][0], pp, vA.x); ffma2(O2[2][1], pp, vA.y);
                ffma2(O2[2][2], pp, vB.x); ffma2(O2[2][3], pp, vB.y);
                pp = pack2(pa.w);
                ffma2(O2[3][0], pp, vA.x); ffma2(O2[3][1], pp, vA.y);
                ffma2(O2[3][2], pp, vB.x); ffma2(O2[3][3], pp, vB.y);
                pp = pack2(pb.x);
                ffma2(O2[4][0], pp, vA.x); ffma2(O2[4][1], pp, vA.y);
                ffma2(O2[4][2], pp, vB.x); ffma2(O2[4][3], pp, vB.y);
                pp = pack2(pb.y);
                ffma2(O2[5][0], pp, vA.x); ffma2(O2[5][1], pp, vA.y);
                ffma2(O2[5][2], pp, vB.x); ffma2(O2[5][3], pp, vB.y);
                pp = pack2(pb.z);
                ffma2(O2[6][0], pp, vA.x); ffma2(O2[6][1], pp, vA.y);
                ffma2(O2[6][2], pp, vB.x); ffma2(O2[6][3], pp, vB.y);
                pp = pack2(pb.w);
                ffma2(O2[7][0], pp, vA.x); ffma2(O2[7][1], pp, vA.y);
                ffma2(O2[7][2], pp, vB.x); ffma2(O2[7][3], pp, vB.y);
            }
        }
    }

    // ---- epilogue: stage through smem, then coalesced y = gamma*(O/l) + x
    __syncthreads();
    float* Ls = Qs;            // 64 floats: 1/l per query row
    float* Os = Ps;            // [c][i] staging, stride OSS (Ps+Vs region, 17664 <= 20992)
    if (cg == 0) {
        Ls[8 * w + 0] = 1.f / lrow[0];
        Ls[8 * w + 1] = 1.f / lrow[1];
        Ls[8 * w + 2] = 1.f / lrow[2];
        Ls[8 * w + 3] = 1.f / lrow[3];
        Ls[8 * w + 4] = 1.f / lrow[4];
        Ls[8 * w + 5] = 1.f / lrow[5];
        Ls[8 * w + 6] = 1.f / lrow[6];
        Ls[8 * w + 7] = 1.f / lrow[7];
    }
    const int cA = 4 * cg;
    const int cB = 128 + 4 * cg;
#pragma unroll
    for (int q = 0; q < 8; q++) {
        const int col = 8 * w + q;
        float2 u;
        u = unpack2(O2[q][0]); Os[(cA)     * OSS + col] = u.x; Os[(cA + 1) * OSS + col] = u.y;
        u = unpack2(O2[q][1]); Os[(cA + 2) * OSS + col] = u.x; Os[(cA + 3) * OSS + col] = u.y;
        u = unpack2(O2[q][2]); Os[(cB)     * OSS + col] = u.x; Os[(cB + 1) * OSS + col] = u.y;
        u = unpack2(O2[q][3]); Os[(cB + 2) * OSS + col] = u.x; Os[(cB + 3) * OSS + col] = u.y;
    }
    __syncthreads();
    const float gm  = gamma[0];
    const float* xb = x   + (size_t)bb * C_ * N_;
    float*       yb = g_y + (size_t)bb * C_ * N_;
    for (int idx = t; idx < 64 * 256; idx += 256) {
        int c = idx >> 6, i = idx & 63;
        yb[c * N_ + n0 + i] = fmaf(gm, Os[c * OSS + i] * Ls[i], xb[c * N_ + n0 + i]);
    }
}

// ---------------- BatchNorm (train mode, batch stats) ----------------
__global__ __launch_bounds__(256) void bn_stats_kernel() {
    const int c = blockIdx.x;
    const int t = threadIdx.x;
    float s = 0.f, sq = 0.f;
    for (int idx = t; idx < B_ * N_; idx += 256) {
        int bb = idx >> 12;
        int n  = idx & (N_ - 1);
        float v = g_y[(size_t)bb * C_ * N_ + (size_t)c * N_ + n];
        s += v; sq += v * v;
    }
#pragma unroll
    for (int off = 16; off > 0; off >>= 1) {
        s  += __shfl_down_sync(0xffffffffu, s, off);
        sq += __shfl_down_sync(0xffffffffu, sq, off);
    }
    __shared__ float rs[8], rq[8];
    if ((t & 31) == 0) { rs[t >> 5] = s; rq[t >> 5] = sq; }
    __syncthreads();
    if (t < 32) {
        s  = (t < 8) ? rs[t] : 0.f;
        sq = (t < 8) ? rq[t] : 0.f;
#pragma unroll
        for (int off = 4; off > 0; off >>= 1) {
            s  += __shfl_down_sync(0xffffffffu, s, off);
            sq += __shfl_down_sync(0xffffffffu, sq, off);
        }
        if (t == 0) {
            const float inv = 1.0f / (float)(B_ * N_);
            float mean = s * inv;
            float var  = sq * inv - mean * mean;
            g_mean[c] = mean;
            g_istd[c] = rsqrtf(var + 1e-5f);
        }
    }
}

__global__ __launch_bounds__(256) void bn_apply_kernel(const float* __restrict__ bnw,
                                                       const float* __restrict__ bnb,
                                                       float* __restrict__ out) {
    size_t idx = ((size_t)blockIdx.x * 256 + threadIdx.x) * 4;
    int c = (int)((idx >> 12) & (C_ - 1));
    float4 v = *(const float4*)&g_y[idx];
    float is = g_istd[c];
    float wv = bnw[c] * is;
    float bv = bnb[c] - g_mean[c] * wv;
    v.x = fmaxf(fmaf(v.x, wv, bv), 0.f);
    v.y = fmaxf(fmaf(v.y, wv, bv), 0.f);
    v.z = fmaxf(fmaf(v.z, wv, bv), 0.f);
    v.w = fmaxf(fmaf(v.w, wv, bv), 0.f);
    *(float4*)&out[idx] = v;
}

// ---------------- launch ----------------
extern "C" void kernel_launch(void* const* d_in, const int* in_sizes, int n_in,
                              void* d_out, int out_size) {
    const float* x     = (const float*)d_in[0];
    const float* wq    = (const float*)d_in[1];
    const float* bq    = (const float*)d_in[2];
    const float* wk    = (const float*)d_in[3];
    const float* bk    = (const float*)d_in[4];
    const float* wv    = (const float*)d_in[5];
    const float* bv    = (const float*)d_in[6];
    const float* gamma = (const float*)d_in[7];
    const float* bnw   = (const float*)d_in[8];
    const float* bnb   = (const float*)d_in[9];
    float* out = (float*)d_out;

    proj2_kernel<0><<<dim3(N_ / 1024, CQK_ / 16, B_), 256>>>(x, wq, bq, CQK_);
    proj2_kernel<1><<<dim3(N_ / 1024, CQK_ / 16, B_), 256>>>(x, wk, bk, CQK_);
    proj2_kernel<2><<<dim3(N_ / 1024, C_   / 16, B_), 256>>>(x, wv, bv, C_);

    cudaFuncSetAttribute(attn_kernel, cudaFuncAttributeMaxDynamicSharedMemorySize, SMEM_ATT_BYTES);
    attn_kernel<<<dim3(N_ / 64, B_), 256, SMEM_ATT_BYTES>>>(x, gamma);

    bn_stats_kernel<<<C_, 256>>>();
    bn_apply_kernel<<<(B_ * C_ * N_) / (256 * 4), 256>>>(bnw, bnb, out);
}

// round 5
// speedup vs baseline: 2.4155x; 1.0031x over previous
#include <cuda_runtime.h>

#define B_   8
#define C_   256
#define N_   4096
#define CQK_ 32

typedef unsigned long long ull;

// ---------------- scratch (static device globals; no allocations) ----------------
__device__ float g_q[(size_t)B_ * CQK_ * N_];   // [b][o][n]
__device__ float g_k[(size_t)B_ * CQK_ * N_];   // [b][o][n]
__device__ float g_v[(size_t)B_ * C_ * N_];     // [b][c][n]
__device__ float g_y[(size_t)B_ * C_ * N_];     // pre-BN residual output
__device__ float g_mean[C_];
__device__ float g_istd[C_];

// ---------------- packed f32x2 helpers (Blackwell FFMA2) ----------------
__device__ __forceinline__ ull pack2(float v) {
    ull r;
    asm("mov.b64 %0, {%1, %1};" : "=l"(r) : "f"(v));
    return r;
}
__device__ __forceinline__ ull packpair(float a, float b) {
    ull r;
    asm("mov.b64 %0, {%1, %2};" : "=l"(r) : "f"(a), "f"(b));
    return r;
}
__device__ __forceinline__ void ffma2(ull& d, ull a, ull b) {
    asm("fma.rn.f32x2 %0, %1, %2, %0;" : "+l"(d) : "l"(a), "l"(b));
}
__device__ __forceinline__ void mul2(ull& d, ull a) {
    asm("mul.rn.f32x2 %0, %0, %1;" : "+l"(d) : "l"(a));
}
__device__ __forceinline__ float2 unpack2(ull v) {
    float2 r;
    asm("mov.b64 {%0, %1}, %2;" : "=f"(r.x), "=f"(r.y) : "l"(v));
    return r;
}

// ---------------- projection GEMM (f32x2, dup-packed weights, 4n/thread) ----------------
// out[b][o][n] = sum_c W[o][c] x[b][c][n] + bias[o]
template<int SEL>
__global__ __launch_bounds__(256) void proj2_kernel(const float* __restrict__ x,
                                                    const float* __restrict__ W,
                                                    const float* __restrict__ bias,
                                                    int Ototal) {
    constexpr int OT = 16;
    float* out = (SEL == 0) ? g_q : (SEL == 1) ? g_k : g_v;
    const int n  = blockIdx.x * 1024 + threadIdx.x * 4;
    const int o0 = blockIdx.y * OT;
    const int bb = blockIdx.z;
    __shared__ ull Ws2[OT * 64];
    ull acc[OT][2];
#pragma unroll
    for (int o = 0; o < OT; o++) { acc[o][0] = 0ull; acc[o][1] = 0ull; }
    const float* xb = x + (size_t)bb * C_ * N_;
#pragma unroll 1
    for (int c0 = 0; c0 < C_; c0 += 64) {
        __syncthreads();
        for (int idx = threadIdx.x; idx < OT * 64; idx += 256) {
            int oo = idx >> 6, cc = idx & 63;
            Ws2[idx] = pack2(W[(o0 + oo) * C_ + c0 + cc]);
        }
        __syncthreads();
#pragma unroll 4
        for (int cc = 0; cc < 64; cc++) {
            float4 xv = *(const float4*)&xb[(size_t)(c0 + cc) * N_ + n];
            ull x01 = packpair(xv.x, xv.y);
            ull x23 = packpair(xv.z, xv.w);
#pragma unroll
            for (int o = 0; o < OT; o++) {
                ull w2 = Ws2[o * 64 + cc];
                ffma2(acc[o][0], w2, x01);
                ffma2(acc[o][1], w2, x23);
            }
        }
    }
    float* ob = out + (size_t)bb * Ototal * N_;
#pragma unroll
    for (int o = 0; o < OT; o++) {
        float bo = bias[o0 + o];
        float2 a = unpack2(acc[o][0]);
        float2 b = unpack2(acc[o][1]);
        float4 r;
        r.x = a.x + bo; r.y = a.y + bo; r.z = b.x + bo; r.w = b.y + bo;
        *(float4*)&ob[(size_t)(o0 + o) * N_ + n] = r;
    }
}

// ---------------- flash attention (fp32, register-blocked 8q x 8c per thread) ----------------
// block 256 = 8 warps. warp w: queries 8w..8w+7. lane cg (0..31): channels {4cg..4cg+3, 128+4cg..+3}.
#define QSS 68
#define KSS 64
#define PSS 68
#define VSS 260
#define OSS 69
constexpr int SMEM_Q = 32 * QSS;    // 2176
constexpr int SMEM_K = 32 * KSS;    // 2048
constexpr int SMEM_P = 64 * PSS;    // 4352
constexpr int SMEM_V = 64 * VSS;    // 16640
constexpr int SMEM_ATT_BYTES = (SMEM_Q + SMEM_K + SMEM_P + SMEM_V) * 4;   // 100864 B

__global__ __launch_bounds__(256, 2) void attn_kernel(const float* __restrict__ x,
                                                      const float* __restrict__ gamma) {
    extern __shared__ float sm[];
    float* Qs = sm;
    float* Ks = Qs + SMEM_Q;
    float* Ps = Ks + SMEM_K;
    float* Vs = Ps + SMEM_P;

    const int t  = threadIdx.x;
    const int w  = t >> 5;
    const int cg = t & 31;
    const int n0 = blockIdx.x * 64;
    const int bb = blockIdx.y;

    const float* qb = g_q + (size_t)bb * CQK_ * N_;
    const float* kb = g_k + (size_t)bb * CQK_ * N_;
    const float* vb = g_v + (size_t)bb * C_ * N_;

    // Q tile: Qs[o][i] <- q[b][o][n0+i]
    for (int idx = t; idx < 32 * 64; idx += 256) {
        int o = idx >> 6, ii = idx & 63;
        Qs[o * QSS + ii] = qb[o * N_ + n0 + ii];
    }

    ull O2[8][4];
#pragma unroll
    for (int q = 0; q < 8; q++)
#pragma unroll
        for (int u = 0; u < 4; u++) O2[q][u] = 0ull;
    float mrow[8], lrow[8];
#pragma unroll
    for (int q = 0; q < 8; q++) { mrow[q] = -1e30f; lrow[q] = 0.f; }

    const int kr_o  = t >> 3;        // K loader: row o (0..31)
    const int kr_j  = (t & 7) * 8;   // K loader: j offset
    const int vr_c  = t >> 3;        // V loader: c row within pass (0..31)
    const int vr_jq = t & 7;         // V loader: j-octet

#pragma unroll 1
    for (int kt = 0; kt < 64; kt++) {
        const int j0 = kt * 64;
        __syncthreads();   // prev PV reads of Ks/Vs/Ps done
        // ---- K tile: Ks[o][j] <- k[b][o][j0+j]
        {
            const float* src = &kb[kr_o * N_ + j0 + kr_j];
            float4 a  = *(const float4*)src;
            float4 b4 = *(const float4*)(src + 4);
            *(float4*)&Ks[kr_o * KSS + kr_j]     = a;
            *(float4*)&Ks[kr_o * KSS + kr_j + 4] = b4;
        }
        // ---- V tile, transposed + XOR-swizzled: Vs[j][c ^ ((j>>3)*4)] <- v[b][c][j0+j]
        {
            const int sw = vr_jq * 4;
#pragma unroll
            for (int pass = 0; pass < 8; pass++) {
                int c = pass * 32 + vr_c;
                const float* src = &vb[(size_t)c * N_ + j0 + vr_jq * 8];
                float4 a  = *(const float4*)src;
                float4 b4 = *(const float4*)(src + 4);
                float* dst = &Vs[(vr_jq * 8) * VSS + (c ^ sw)];
                dst[0 * VSS] = a.x;  dst[1 * VSS] = a.y;
                dst[2 * VSS] = a.z;  dst[3 * VSS] = a.w;
                dst[4 * VSS] = b4.x; dst[5 * VSS] = b4.y;
                dst[6 * VSS] = b4.z; dst[7 * VSS] = b4.w;
            }
        }
        __syncthreads();

        // ---- QK: S[8 queries][2 js] per lane; j = 2cg, 2cg+1
        ull Sj0[4], Sj1[4];
#pragma unroll
        for (int p = 0; p < 4; p++) { Sj0[p] = 0ull; Sj1[p] = 0ull; }
        {
            const float* qsw = Qs + 8 * w;
            const float* ksl = Ks + 2 * cg;
#pragma unroll 8
            for (int o = 0; o < 32; o++) {
                float2 kv = *(const float2*)(ksl + o * KSS);
                ulonglong2 qA = *(const ulonglong2*)(qsw + o * QSS);
                ulonglong2 qB = *(const ulonglong2*)(qsw + o * QSS + 4);
                ull k0 = pack2(kv.x), k1 = pack2(kv.y);
                ffma2(Sj0[0], qA.x, k0); ffma2(Sj0[1], qA.y, k0);
                ffma2(Sj0[2], qB.x, k0); ffma2(Sj0[3], qB.y, k0);
                ffma2(Sj1[0], qA.x, k1); ffma2(Sj1[1], qA.y, k1);
                ffma2(Sj1[2], qB.x, k1); ffma2(Sj1[3], qB.y, k1);
            }
        }
        float s[8][2];
#pragma unroll
        for (int p = 0; p < 4; p++) {
            float2 u0 = unpack2(Sj0[p]);
            float2 u1 = unpack2(Sj1[p]);
            s[2 * p][0]     = u0.x; s[2 * p + 1][0] = u0.y;
            s[2 * p][1]     = u1.x; s[2 * p + 1][1] = u1.y;
        }

        // ---- online softmax (row reduction across full warp)
        float P[8][2];
#pragma unroll
        for (int q = 0; q < 8; q++) {
            float rm = fmaxf(s[q][0], s[q][1]);
#pragma unroll
            for (int off = 16; off > 0; off >>= 1)
                rm = fmaxf(rm, __shfl_xor_sync(0xffffffffu, rm, off));
            float mn    = fmaxf(mrow[q], rm);
            float alpha = __expf(mrow[q] - mn);
            float e0 = __expf(s[q][0] - mn);
            float e1 = __expf(s[q][1] - mn);
            float rs = e0 + e1;
#pragma unroll
            for (int off = 16; off > 0; off >>= 1)
                rs += __shfl_xor_sync(0xffffffffu, rs, off);
            lrow[q] = lrow[q] * alpha + rs;
            mrow[q] = mn;
            P[q][0] = e0; P[q][1] = e1;
            ull av = pack2(alpha);
            mul2(O2[q][0], av); mul2(O2[q][1], av);
            mul2(O2[q][2], av); mul2(O2[q][3], av);
        }
        // ---- write P: Ps[j][i]  (lane owns js 2cg, 2cg+1; queries 8w..8w+7 consecutive)
#pragma unroll
        for (int jj = 0; jj < 2; jj++) {
            float4 pa, pb;
            pa.x = P[0][jj]; pa.y = P[1][jj]; pa.z = P[2][jj]; pa.w = P[3][jj];
            pb.x = P[4][jj]; pb.y = P[5][jj]; pb.z = P[6][jj]; pb.w = P[7][jj];
            float* d = &Ps[(2 * cg + jj) * PSS + 8 * w];
            *(float4*)d       = pa;
            *(float4*)(d + 4) = pb;
        }
        __syncthreads();

        // ---- PV: O[q][c] += P[j][q] * V[j][c]
#pragma unroll 1
        for (int jo = 0; jo < 8; jo++) {
            const float* vrow = Vs + (jo * 8) * VSS + ((cg ^ jo) << 2);
            const float* prow = Ps + (jo * 8) * PSS + 8 * w;
#pragma unroll 2
            for (int m = 0; m < 8; m++) {
                float4 pa = *(const float4*)(prow + m * PSS);
                float4 pb = *(const float4*)(prow + m * PSS + 4);
                ulonglong2 vA = *(const ulonglong2*)(vrow + m * VSS);
                ulonglong2 vB = *(const ulonglong2*)(vrow + m * VSS + 128);
                ull pp;
                pp = pack2(pa.x);
                ffma2(O2[0][0], pp, vA.x); ffma2(O2[0][1], pp, vA.y);
                ffma2(O2[0][2], pp, vB.x); ffma2(O2[0][3], pp, vB.y);
                pp = pack2(pa.y);
                ffma2(O2[1][0], pp, vA.x); ffma2(O2[1][1], pp, vA.y);
                ffma2(O2[1][2], pp, vB.x); ffma2(O2[1][3], pp, vB.y);
                pp = pack2(pa.z);
                ffma2(O2[2][0], pp, vA.x); ffma2(O2[2][1], pp, vA.y);
                ffma2(O2[2][2], pp, vB.x); ffma2(O2[2][3], pp, vB.y);
                pp = pack2(pa.w);
                ffma2(O2[3][0], pp, vA.x); ffma2(O2[3][1], pp, vA.y);
                ffma2(O2[3][2], pp, vB.x); ffma2(O2[3][3], pp, vB.y);
                pp = pack2(pb.x);
                ffma2(O2[4][0], pp, vA.x); ffma2(O2[4][1], pp, vA.y);
                ffma2(O2[4][2], pp, vB.x); ffma2(O2[4][3], pp, vB.y);
                pp = pack2(pb.y);
                ffma2(O2[5][0], pp, vA.x); ffma2(O2[5][1], pp, vA.y);
                ffma2(O2[5][2], pp, vB.x); ffma2(O2[5][3], pp, vB.y);
                pp = pack2(pb.z);
                ffma2(O2[6][0], pp, vA.x); ffma2(O2[6][1], pp, vA.y);
                ffma2(O2[6][2], pp, vB.x); ffma2(O2[6][3], pp, vB.y);
                pp = pack2(pb.w);
                ffma2(O2[7][0], pp, vA.x); ffma2(O2[7][1], pp, vA.y);
                ffma2(O2[7][2], pp, vB.x); ffma2(O2[7][3], pp, vB.y);
            }
        }
    }

    // ---- epilogue: stage through smem, then coalesced y = gamma*(O/l) + x
    __syncthreads();
    float* Ls = Qs;            // 64 floats: 1/l per query row
    float* Os = Ps;            // [c][i] staging, stride OSS (Ps+Vs region, 17664 <= 20992)
    if (cg == 0) {
        Ls[8 * w + 0] = 1.f / lrow[0];
        Ls[8 * w + 1] = 1.f / lrow[1];
        Ls[8 * w + 2] = 1.f / lrow[2];
        Ls[8 * w + 3] = 1.f / lrow[3];
        Ls[8 * w + 4] = 1.f / lrow[4];
        Ls[8 * w + 5] = 1.f / lrow[5];
        Ls[8 * w + 6] = 1.f / lrow[6];
        Ls[8 * w + 7] = 1.f / lrow[7];
    }
    const int cA = 4 * cg;
    const int cB = 128 + 4 * cg;
#pragma unroll
    for (int q = 0; q < 8; q++) {
        const int col = 8 * w + q;
        float2 u;
        u = unpack2(O2[q][0]); Os[(cA)     * OSS + col] = u.x; Os[(cA + 1) * OSS + col] = u.y;
        u = unpack2(O2[q][1]); Os[(cA + 2) * OSS + col] = u.x; Os[(cA + 3) * OSS + col] = u.y;
        u = unpack2(O2[q][2]); Os[(cB)     * OSS + col] = u.x; Os[(cB + 1) * OSS + col] = u.y;
        u = unpack2(O2[q][3]); Os[(cB + 2) * OSS + col] = u.x; Os[(cB + 3) * OSS + col] = u.y;
    }
    __syncthreads();
    const float gm  = gamma[0];
    const float* xb = x   + (size_t)bb * C_ * N_;
    float*       yb = g_y + (size_t)bb * C_ * N_;
    for (int idx = t; idx < 64 * 256; idx += 256) {
        int c = idx >> 6, i = idx & 63;
        yb[c * N_ + n0 + i] = fmaf(gm, Os[c * OSS + i] * Ls[i], xb[c * N_ + n0 + i]);
    }
}

// ---------------- BatchNorm (train mode, batch stats) ----------------
__global__ __launch_bounds__(256) void bn_stats_kernel() {
    const int c = blockIdx.x;
    const int t = threadIdx.x;
    float s = 0.f, sq = 0.f;
    for (int idx = t; idx < B_ * N_; idx += 256) {
        int bb = idx >> 12;
        int n  = idx & (N_ - 1);
        float v = g_y[(size_t)bb * C_ * N_ + (size_t)c * N_ + n];
        s += v; sq += v * v;
    }
#pragma unroll
    for (int off = 16; off > 0; off >>= 1) {
        s  += __shfl_down_sync(0xffffffffu, s, off);
        sq += __shfl_down_sync(0xffffffffu, sq, off);
    }
    __shared__ float rs[8], rq[8];
    if ((t & 31) == 0) { rs[t >> 5] = s; rq[t >> 5] = sq; }
    __syncthreads();
    if (t < 32) {
        s  = (t < 8) ? rs[t] : 0.f;
        sq = (t < 8) ? rq[t] : 0.f;
#pragma unroll
        for (int off = 4; off > 0; off >>= 1) {
            s  += __shfl_down_sync(0xffffffffu, s, off);
            sq += __shfl_down_sync(0xffffffffu, sq, off);
        }
        if (t == 0) {
            const float inv = 1.0f / (float)(B_ * N_);
            float mean = s * inv;
            float var  = sq * inv - mean * mean;
            g_mean[c] = mean;
            g_istd[c] = rsqrtf(var + 1e-5f);
        }
    }
}

__global__ __launch_bounds__(256) void bn_apply_kernel(const float* __restrict__ bnw,
                                                       const float* __restrict__ bnb,
                                                       float* __restrict__ out) {
    size_t idx = ((size_t)blockIdx.x * 256 + threadIdx.x) * 4;
    int c = (int)((idx >> 12) & (C_ - 1));
    float4 v = *(const float4*)&g_y[idx];
    float is = g_istd[c];
    float wv = bnw[c] * is;
    float bv = bnb[c] - g_mean[c] * wv;
    v.x = fmaxf(fmaf(v.x, wv, bv), 0.f);
    v.y = fmaxf(fmaf(v.y, wv, bv), 0.f);
    v.z = fmaxf(fmaf(v.z, wv, bv), 0.f);
    v.w = fmaxf(fmaf(v.w, wv, bv), 0.f);
    *(float4*)&out[idx] = v;
}

// ---------------- launch ----------------
extern "C" void kernel_launch(void* const* d_in, const int* in_sizes, int n_in,
                              void* d_out, int out_size) {
    const float* x     = (const float*)d_in[0];
    const float* wq    = (const float*)d_in[1];
    const float* bq    = (const float*)d_in[2];
    const float* wk    = (const float*)d_in[3];
    const float* bk    = (const float*)d_in[4];
    const float* wv    = (const float*)d_in[5];
    const float* bv    = (const float*)d_in[6];
    const float* gamma = (const float*)d_in[7];
    const float* bnw   = (const float*)d_in[8];
    const float* bnb   = (const float*)d_in[9];
    float* out = (float*)d_out;

    proj2_kernel<0><<<dim3(N_ / 1024, CQK_ / 16, B_), 256>>>(x, wq, bq, CQK_);
    proj2_kernel<1><<<dim3(N_ / 1024, CQK_ / 16, B_), 256>>>(x, wk, bk, CQK_);
    proj2_kernel<2><<<dim3(N_ / 1024, C_   / 16, B_), 256>>>(x, wv, bv, C_);

    cudaFuncSetAttribute(attn_kernel, cudaFuncAttributeMaxDynamicSharedMemorySize, SMEM_ATT_BYTES);
    attn_kernel<<<dim3(N_ / 64, B_), 256, SMEM_ATT_BYTES>>>(x, gamma);

    bn_stats_kernel<<<C_, 256>>>();
    bn_apply_kernel<<<(B_ * C_ * N_) / (256 * 4), 256>>>(bnw, bnb, out);
}

// round 7
// speedup vs baseline: 4.1228x; 1.7068x over previous
#include <cuda_runtime.h>
#include <cuda_bf16.h>

#define B_   8
#define C_   256
#define N_   4096
#define JT   64
#define NT   (N_ / JT)

typedef unsigned int u32;
typedef unsigned long long ull;

// ---------------- scratch (static device globals; no allocations) ----------------
__device__ __nv_bfloat16 g_qs[(size_t)B_ * N_ * 64];   // [b][n][Qh(32)|Ql(32)]
__device__ __nv_bfloat16 g_ks[(size_t)B_ * N_ * 64];   // [b][n][Kh|Kl]
__device__ __nv_bfloat16 g_vh[(size_t)B_ * C_ * N_];   // [b][c][n]
__device__ __nv_bfloat16 g_vl[(size_t)B_ * C_ * N_];
__device__ float g_y[(size_t)B_ * C_ * N_];
__device__ float g_mean[C_], g_istd[C_];

// ---------------- PTX helpers (all baseline sm_80+, no 'a'-gated features) ----------------
__device__ __forceinline__ u32 smem_u32(const void* p) {
    u32 a;
    asm("{ .reg .u64 t; cvta.to.shared.u64 t, %1; cvt.u32.u64 %0, t; }" : "=r"(a) : "l"(p));
    return a;
}
__device__ __forceinline__ void ldsm4(u32* r, u32 a) {
    asm volatile("ldmatrix.sync.aligned.m8n8.x4.shared.b16 {%0,%1,%2,%3}, [%4];"
        : "=r"(r[0]), "=r"(r[1]), "=r"(r[2]), "=r"(r[3]) : "r"(a));
}
__device__ __forceinline__ void mma_bf16(float* d, const u32* a, const u32* b) {
    asm volatile("mma.sync.aligned.m16n8k16.row.col.f32.bf16.bf16.f32 "
        "{%0,%1,%2,%3}, {%4,%5,%6,%7}, {%8,%9}, {%0,%1,%2,%3};"
        : "+f"(d[0]), "+f"(d[1]), "+f"(d[2]), "+f"(d[3])
        : "r"(a[0]), "r"(a[1]), "r"(a[2]), "r"(a[3]), "r"(b[0]), "r"(b[1]));
}
__device__ __forceinline__ void cpa16(u32 d, const void* s) {
    asm volatile("cp.async.cg.shared.global [%0], [%1], 16;" :: "r"(d), "l"(s));
}
#define CP_COMMIT() asm volatile("cp.async.commit_group;" ::: "memory")
#define CP_WAIT1()  asm volatile("cp.async.wait_group 1;" ::: "memory")
#define CP_WAIT0()  asm volatile("cp.async.wait_group 0;" ::: "memory")

// ---------------- f32x2 helpers ----------------
__device__ __forceinline__ ull pack2(float v) { ull r; asm("mov.b64 %0, {%1, %1};" : "=l"(r) : "f"(v)); return r; }
__device__ __forceinline__ ull packpair(float a, float b) { ull r; asm("mov.b64 %0, {%1, %2};" : "=l"(r) : "f"(a), "f"(b)); return r; }
__device__ __forceinline__ void ffma2(ull& d, ull a, ull b) { asm("fma.rn.f32x2 %0, %1, %2, %0;" : "+l"(d) : "l"(a), "l"(b)); }
__device__ __forceinline__ float2 unpack2(ull v) { float2 r; asm("mov.b64 {%0, %1}, %2;" : "=f"(r.x), "=f"(r.y) : "l"(v)); return r; }

// ---------------- Q/K projection -> split-bf16 [b][n][hi|lo] ----------------
template<int SEL>
__global__ __launch_bounds__(256) void proj_qk_kernel(const float* __restrict__ x,
                                                      const float* __restrict__ W,
                                                      const float* __restrict__ bias) {
    constexpr int OT = 16;
    __nv_bfloat16* out = SEL ? g_ks : g_qs;
    const int n  = blockIdx.x * 1024 + threadIdx.x * 4;
    const int o0 = blockIdx.y * OT;
    const int bb = blockIdx.z;
    __shared__ ull Ws2[OT * 64];
    ull acc[OT][2];
#pragma unroll
    for (int o = 0; o < OT; o++) { acc[o][0] = 0ull; acc[o][1] = 0ull; }
    const float* xb = x + (size_t)bb * C_ * N_;
#pragma unroll 1
    for (int c0 = 0; c0 < C_; c0 += 64) {
        __syncthreads();
        for (int idx = threadIdx.x; idx < OT * 64; idx += 256)
            Ws2[idx] = pack2(W[(o0 + (idx >> 6)) * C_ + c0 + (idx & 63)]);
        __syncthreads();
#pragma unroll 4
        for (int cc = 0; cc < 64; cc++) {
            float4 xv = *(const float4*)&xb[(size_t)(c0 + cc) * N_ + n];
            ull x01 = packpair(xv.x, xv.y), x23 = packpair(xv.z, xv.w);
#pragma unroll
            for (int o = 0; o < OT; o++) {
                ull w2 = Ws2[o * 64 + cc];
                ffma2(acc[o][0], w2, x01);
                ffma2(acc[o][1], w2, x23);
            }
        }
    }
    unsigned short hs[4][OT], ls[4][OT];
#pragma unroll
    for (int o = 0; o < OT; o++) {
        float bo = bias[o0 + o];
        float2 a = unpack2(acc[o][0]), b = unpack2(acc[o][1]);
        float v[4] = {a.x + bo, a.y + bo, b.x + bo, b.y + bo};
#pragma unroll
        for (int e = 0; e < 4; e++) {
            __nv_bfloat16 hi = __float2bfloat16(v[e]);
            __nv_bfloat16 lo = __float2bfloat16(v[e] - __bfloat162float(hi));
            hs[e][o] = __bfloat16_as_ushort(hi);
            ls[e][o] = __bfloat16_as_ushort(lo);
        }
    }
    u32* ob = (u32*)out;
#pragma unroll
    for (int e = 0; e < 4; e++) {
        size_t rb = ((size_t)bb * N_ + n + e) * 32;
#pragma unroll
        for (int op = 0; op < 8; op++) {
            ob[rb + (o0 >> 1) + op]      = ((u32)hs[e][2 * op + 1] << 16) | hs[e][2 * op];
            ob[rb + 16 + (o0 >> 1) + op] = ((u32)ls[e][2 * op + 1] << 16) | ls[e][2 * op];
        }
    }
}

// ---------------- V projection -> split-bf16 planes [b][c][n] ----------------
__global__ __launch_bounds__(256) void proj_v_kernel(const float* __restrict__ x,
                                                     const float* __restrict__ W,
                                                     const float* __restrict__ bias) {
    constexpr int OT = 16;
    const int n  = blockIdx.x * 1024 + threadIdx.x * 4;
    const int o0 = blockIdx.y * OT;
    const int bb = blockIdx.z;
    __shared__ ull Ws2[OT * 64];
    ull acc[OT][2];
#pragma unroll
    for (int o = 0; o < OT; o++) { acc[o][0] = 0ull; acc[o][1] = 0ull; }
    const float* xb = x + (size_t)bb * C_ * N_;
#pragma unroll 1
    for (int c0 = 0; c0 < C_; c0 += 64) {
        __syncthreads();
        for (int idx = threadIdx.x; idx < OT * 64; idx += 256)
            Ws2[idx] = pack2(W[(o0 + (idx >> 6)) * C_ + c0 + (idx & 63)]);
        __syncthreads();
#pragma unroll 4
        for (int cc = 0; cc < 64; cc++) {
            float4 xv = *(const float4*)&xb[(size_t)(c0 + cc) * N_ + n];
            ull x01 = packpair(xv.x, xv.y), x23 = packpair(xv.z, xv.w);
#pragma unroll
            for (int o = 0; o < OT; o++) {
                ull w2 = Ws2[o * 64 + cc];
                ffma2(acc[o][0], w2, x01);
                ffma2(acc[o][1], w2, x23);
            }
        }
    }
#pragma unroll
    for (int o = 0; o < OT; o++) {
        float bo = bias[o0 + o];
        float2 a = unpack2(acc[o][0]), b = unpack2(acc[o][1]);
        float v[4] = {a.x + bo, a.y + bo, b.x + bo, b.y + bo};
        unsigned short hv[4], lv[4];
#pragma unroll
        for (int e = 0; e < 4; e++) {
            __nv_bfloat16 hi = __float2bfloat16(v[e]);
            __nv_bfloat16 lo = __float2bfloat16(v[e] - __bfloat162float(hi));
            hv[e] = __bfloat16_as_ushort(hi);
            lv[e] = __bfloat16_as_ushort(lo);
        }
        size_t base = ((size_t)bb * C_ + o0 + o) * N_ + n;
        uint2 uh, ul;
        uh.x = ((u32)hv[1] << 16) | hv[0]; uh.y = ((u32)hv[3] << 16) | hv[2];
        ul.x = ((u32)lv[1] << 16) | lv[0]; ul.y = ((u32)lv[3] << 16) | lv[2];
        *(uint2*)&g_vh[base] = uh;
        *(uint2*)&g_vl[base] = ul;
    }
}

// ---------------- HMMA flash attention (split-bf16, mma.sync m16n8k16) ----------------
// CTA: 64 queries x 128 channels. 8 warps: warp w -> rows (w&3)*16, ch half (w>>2)*64.
// Smem (144B row stride, conflict-free ldmatrix): Q 9216 | K x2 stages | Vh+Vl x2 stages.
constexpr int KOFF = 9216;
constexpr int KSTG = 9216;
constexpr int VOFF = KOFF + 2 * KSTG;    // 27648
constexpr int VSTG = 36864;              // Vh 18432 + Vl 18432
constexpr int SMEM_AT = VOFF + 2 * VSTG; // 101376

__global__ __launch_bounds__(256, 2) void attn_kernel(const float* __restrict__ x,
                                                      const float* __restrict__ gamma) {
    extern __shared__ char smc[];
    const u32 sb = smem_u32(smc);
    const int t = threadIdx.x, w = t >> 5, lid = t & 31;
    const int r0 = (w & 3) * 16, hf = w >> 2;
    const int g = lid >> 2, qt = lid & 3;
    const int rw = lid & 7, mi = lid >> 3;
    const int n0 = blockIdx.x * 64, chb = blockIdx.y * 128, bb = blockIdx.z;

    const __nv_bfloat16* qg  = g_qs + (size_t)bb * N_ * 64;
    const __nv_bfloat16* kgm = g_ks + (size_t)bb * N_ * 64;
    const __nv_bfloat16* vhb = g_vh + ((size_t)bb * C_ + chb) * N_;
    const __nv_bfloat16* vlb = g_vl + ((size_t)bb * C_ + chb) * N_;

    // Q -> smem (plain)
#pragma unroll
    for (int p = 0; p < 2; p++) {
        int ck = t + p * 256; int row = ck >> 3, col = ck & 7;
        *(uint4*)(smc + row * 144 + col * 16) = *(const uint4*)(qg + (size_t)(n0 + row) * 64 + col * 8);
    }
    // prefetch stage 0
    {
        u32 sk = sb + KOFF, sv = sb + VOFF;
#pragma unroll
        for (int p = 0; p < 2; p++) {
            int ck = t + p * 256; int row = ck >> 3, col = ck & 7;
            cpa16(sk + row * 144 + col * 16, kgm + (size_t)row * 64 + col * 8);
        }
#pragma unroll
        for (int p = 0; p < 4; p++) {
            int cv = t + p * 256; int cr = cv >> 3, col = cv & 7;
            u32 doff = cr * 144 + col * 16;
            cpa16(sv + doff,         vhb + (size_t)cr * N_ + col * 8);
            cpa16(sv + 18432 + doff, vlb + (size_t)cr * N_ + col * 8);
        }
        CP_COMMIT();
    }
    __syncthreads();

    // Q fragments (resident whole kernel): hi tiles cols 0-31, lo tiles 32-63
    u32 QA[16];
    {
        u32 qa = sb + (u32)(r0 + (mi & 1) * 8 + rw) * 144 + (u32)(mi >> 1) * 16;
        ldsm4(QA + 0, qa);       // Qh dims 0-15
        ldsm4(QA + 4, qa + 32);  // Qh dims 16-31
        ldsm4(QA + 8, qa + 64);  // Ql dims 0-15
        ldsm4(QA + 12, qa + 96); // Ql dims 16-31
    }
    float O[32];
#pragma unroll
    for (int i = 0; i < 32; i++) O[i] = 0.f;
    float m0 = -1e30f, m1 = -1e30f, ls0 = 0.f, ls1 = 0.f;

#pragma unroll 1
    for (int kt = 0; kt < NT; kt++) {
        // prefetch kt+1 (stage freed by end-of-prev-iter barrier)
        if (kt + 1 < NT) {
            const int st = (kt + 1) & 1, j0 = (kt + 1) * JT;
            u32 sk = sb + KOFF + st * KSTG, sv = sb + VOFF + st * VSTG;
#pragma unroll
            for (int p = 0; p < 2; p++) {
                int ck = t + p * 256; int row = ck >> 3, col = ck & 7;
                cpa16(sk + row * 144 + col * 16, kgm + (size_t)(j0 + row) * 64 + col * 8);
            }
#pragma unroll
            for (int p = 0; p < 4; p++) {
                int cv = t + p * 256; int cr = cv >> 3, col = cv & 7;
                u32 doff = cr * 144 + col * 16;
                cpa16(sv + doff,         vhb + (size_t)cr * N_ + j0 + col * 8);
                cpa16(sv + 18432 + doff, vlb + (size_t)cr * N_ + j0 + col * 8);
            }
            CP_COMMIT();
            CP_WAIT1();
        } else {
            CP_WAIT0();
        }
        __syncthreads();

        const int st = kt & 1;
        const u32 sk = sb + KOFF + st * KSTG;
        const u32 sv = sb + VOFF + st * VSTG;

        // ---- QK: S[16 rows x 64 keys] per warp (8 n8 tiles), 3 split products
        float S[32];
#pragma unroll
        for (int i = 0; i < 32; i++) S[i] = 0.f;
        {
            u32 ka = sk + (u32)rw * 144 + (u32)mi * 16;
#pragma unroll
            for (int kgi = 0; kgi < 8; kgi++) {
                u32 kb[8];
                ldsm4(kb, ka);        // Kh: dims 0-15, 16-31
                ldsm4(kb + 4, ka + 64); // Kl: dims 32-47, 48-63 (logical 0-15, 16-31)
                ka += 1152;
                float* S4 = S + kgi * 4;
                mma_bf16(S4, QA + 0,  kb + 0);
                mma_bf16(S4, QA + 4,  kb + 2);
                mma_bf16(S4, QA + 0,  kb + 4);
                mma_bf16(S4, QA + 4,  kb + 6);
                mma_bf16(S4, QA + 8,  kb + 0);
                mma_bf16(S4, QA + 12, kb + 2);
            }
        }
        // ---- online softmax (rows g, g+8; quad-shuffle reductions)
        u32 PH[16], PL[16];
        {
            float tm0 = -1e30f, tm1 = -1e30f;
#pragma unroll
            for (int kgi = 0; kgi < 8; kgi++) {
                tm0 = fmaxf(tm0, fmaxf(S[4 * kgi],     S[4 * kgi + 1]));
                tm1 = fmaxf(tm1, fmaxf(S[4 * kgi + 2], S[4 * kgi + 3]));
            }
            tm0 = fmaxf(tm0, __shfl_xor_sync(0xffffffffu, tm0, 1));
            tm0 = fmaxf(tm0, __shfl_xor_sync(0xffffffffu, tm0, 2));
            tm1 = fmaxf(tm1, __shfl_xor_sync(0xffffffffu, tm1, 1));
            tm1 = fmaxf(tm1, __shfl_xor_sync(0xffffffffu, tm1, 2));
            float mn0 = fmaxf(m0, tm0), mn1 = fmaxf(m1, tm1);
            float al0 = __expf(m0 - mn0), al1 = __expf(m1 - mn1);
            m0 = mn0; m1 = mn1;
            ls0 *= al0; ls1 *= al1;
#pragma unroll
            for (int nt = 0; nt < 8; nt++) {
                O[4 * nt]     *= al0; O[4 * nt + 1] *= al0;
                O[4 * nt + 2] *= al1; O[4 * nt + 3] *= al1;
            }
#pragma unroll
            for (int kgi = 0; kgi < 8; kgi++) {
                float e0 = __expf(S[4 * kgi]     - mn0);
                float e1 = __expf(S[4 * kgi + 1] - mn0);
                float e2 = __expf(S[4 * kgi + 2] - mn1);
                float e3 = __expf(S[4 * kgi + 3] - mn1);
                ls0 += e0 + e1; ls1 += e2 + e3;
                __nv_bfloat16 h0 = __float2bfloat16(e0), h1 = __float2bfloat16(e1);
                __nv_bfloat16 h2 = __float2bfloat16(e2), h3 = __float2bfloat16(e3);
                PH[2 * kgi]     = ((u32)__bfloat16_as_ushort(h1) << 16) | __bfloat16_as_ushort(h0);
                PH[2 * kgi + 1] = ((u32)__bfloat16_as_ushort(h3) << 16) | __bfloat16_as_ushort(h2);
                __nv_bfloat16 q0b = __float2bfloat16(e0 - __bfloat162float(h0));
                __nv_bfloat16 q1b = __float2bfloat16(e1 - __bfloat162float(h1));
                __nv_bfloat16 q2b = __float2bfloat16(e2 - __bfloat162float(h2));
                __nv_bfloat16 q3b = __float2bfloat16(e3 - __bfloat162float(h3));
                PL[2 * kgi]     = ((u32)__bfloat16_as_ushort(q1b) << 16) | __bfloat16_as_ushort(q0b);
                PL[2 * kgi + 1] = ((u32)__bfloat16_as_ushort(q3b) << 16) | __bfloat16_as_ushort(q2b);
            }
        }
        // ---- PV: O += P * V (4 k16 chunks x 8 n8 ch tiles x 3 products)
        {
            u32 vb0 = sv + (u32)(hf * 64 + (mi >> 1) * 8 + rw) * 144 + (u32)(mi & 1) * 16;
#pragma unroll
            for (int c = 0; c < 4; c++) {
                const u32* pha = PH + 4 * c;
                const u32* pla = PL + 4 * c;
#pragma unroll
                for (int a = 0; a < 4; a++) {
                    u32 vh4[4], vl4[4];
                    ldsm4(vh4, vb0 + a * 2304 + c * 32);
                    ldsm4(vl4, vb0 + 18432 + a * 2304 + c * 32);
                    float* Oa = O + a * 8;
                    mma_bf16(Oa,     pha, vh4 + 0);
                    mma_bf16(Oa,     pha, vl4 + 0);
                    mma_bf16(Oa,     pla, vh4 + 0);
                    mma_bf16(Oa + 4, pha, vh4 + 2);
                    mma_bf16(Oa + 4, pha, vl4 + 2);
                    mma_bf16(Oa + 4, pla, vh4 + 2);
                }
            }
        }
        __syncthreads();   // all warps done with stage kt -> safe to prefetch over it
    }

    // ---- epilogue
    ls0 += __shfl_xor_sync(0xffffffffu, ls0, 1);
    ls0 += __shfl_xor_sync(0xffffffffu, ls0, 2);
    ls1 += __shfl_xor_sync(0xffffffffu, ls1, 1);
    ls1 += __shfl_xor_sync(0xffffffffu, ls1, 2);
    const float gm = gamma[0];
    const float li0 = gm / ls0, li1 = gm / ls1;
    float* Os = (float*)(smc + VOFF);   // [128 ch][68] staging (34816B <= stage area)
#pragma unroll
    for (int nt = 0; nt < 8; nt++) {
        int cw = hf * 64 + nt * 8 + 2 * qt;
        Os[cw * 68 + r0 + g]           = O[4 * nt] * li0;
        Os[(cw + 1) * 68 + r0 + g]     = O[4 * nt + 1] * li0;
        Os[cw * 68 + r0 + g + 8]       = O[4 * nt + 2] * li1;
        Os[(cw + 1) * 68 + r0 + g + 8] = O[4 * nt + 3] * li1;
    }
    __syncthreads();
    {
        const int ch = t >> 1, q0 = (t & 1) * 32;
        const float* orow = Os + ch * 68 + q0;
        const float* xr = x   + ((size_t)bb * C_ + chb + ch) * N_ + n0 + q0;
        float*       yr = g_y + ((size_t)bb * C_ + chb + ch) * N_ + n0 + q0;
#pragma unroll
        for (int i = 0; i < 32; i += 4) {
            float4 ov = *(const float4*)(orow + i);
            float4 xv = *(const float4*)(xr + i);
            float4 yv;
            yv.x = ov.x + xv.x; yv.y = ov.y + xv.y;
            yv.z = ov.z + xv.z; yv.w = ov.w + xv.w;
            *(float4*)(yr + i) = yv;
        }
    }
}

// ---------------- BatchNorm ----------------
__global__ __launch_bounds__(256) void bn_stats_kernel() {
    const int c = blockIdx.x, t = threadIdx.x;
    float s = 0.f, sq = 0.f;
    for (int idx = t; idx < B_ * N_; idx += 256) {
        float v = g_y[(size_t)(idx >> 12) * C_ * N_ + (size_t)c * N_ + (idx & (N_ - 1))];
        s += v; sq += v * v;
    }
#pragma unroll
    for (int off = 16; off > 0; off >>= 1) {
        s  += __shfl_down_sync(0xffffffffu, s, off);
        sq += __shfl_down_sync(0xffffffffu, sq, off);
    }
    __shared__ float rs[8], rq[8];
    if ((t & 31) == 0) { rs[t >> 5] = s; rq[t >> 5] = sq; }
    __syncthreads();
    if (t < 32) {
        s  = (t < 8) ? rs[t] : 0.f;
        sq = (t < 8) ? rq[t] : 0.f;
#pragma unroll
        for (int off = 4; off > 0; off >>= 1) {
            s  += __shfl_down_sync(0xffffffffu, s, off);
            sq += __shfl_down_sync(0xffffffffu, sq, off);
        }
        if (t == 0) {
            const float inv = 1.0f / (float)(B_ * N_);
            float mean = s * inv;
            float var  = sq * inv - mean * mean;
            g_mean[c] = mean;
            g_istd[c] = rsqrtf(var + 1e-5f);
        }
    }
}

__global__ __launch_bounds__(256) void bn_apply_kernel(const float* __restrict__ bnw,
                                                       const float* __restrict__ bnb,
                                                       float* __restrict__ out) {
    size_t idx = ((size_t)blockIdx.x * 256 + threadIdx.x) * 4;
    int c = (int)((idx >> 12) & (C_ - 1));
    float4 v = *(const float4*)&g_y[idx];
    float is = g_istd[c];
    float wv = bnw[c] * is;
    float bv = bnb[c] - g_mean[c] * wv;
    v.x = fmaxf(fmaf(v.x, wv, bv), 0.f);
    v.y = fmaxf(fmaf(v.y, wv, bv), 0.f);
    v.z = fmaxf(fmaf(v.z, wv, bv), 0.f);
    v.w = fmaxf(fmaf(v.w, wv, bv), 0.f);
    *(float4*)&out[idx] = v;
}

// ---------------- launch ----------------
extern "C" void kernel_launch(void* const* d_in, const int* in_sizes, int n_in,
                              void* d_out, int out_size) {
    const float* x     = (const float*)d_in[0];
    const float* wq    = (const float*)d_in[1];
    const float* bq    = (const float*)d_in[2];
    const float* wk    = (const float*)d_in[3];
    const float* bk    = (const float*)d_in[4];
    const float* wv    = (const float*)d_in[5];
    const float* bv    = (const float*)d_in[6];
    const float* gamma = (const float*)d_in[7];
    const float* bnw   = (const float*)d_in[8];
    const float* bnb   = (const float*)d_in[9];
    float* out = (float*)d_out;

    proj_qk_kernel<0><<<dim3(N_ / 1024, 2, B_), 256>>>(x, wq, bq);
    proj_qk_kernel<1><<<dim3(N_ / 1024, 2, B_), 256>>>(x, wk, bk);
    proj_v_kernel<<<dim3(N_ / 1024, C_ / 16, B_), 256>>>(x, wv, bv);

    cudaFuncSetAttribute(attn_kernel, cudaFuncAttributeMaxDynamicSharedMemorySize, SMEM_AT);
    attn_kernel<<<dim3(N_ / 64, 2, B_), 256, SMEM_AT>>>(x, gamma);

    bn_stats_kernel<<<C_, 256>>>();
    bn_apply_kernel<<<(B_ * C_ * N_) / (256 * 4), 256>>>(bnw, bnb, out);
}

// round 11
// speedup vs baseline: 4.7871x; 1.1611x over previous
#include <cuda_runtime.h>
#include <cuda_bf16.h>

#define B_   8
#define C_   256
#define N_   4096
#define JT   64
#define NT   (N_ / JT)

typedef unsigned int u32;
typedef unsigned long long ull;

// ---------------- scratch (static device globals; no allocations) ----------------
__device__ __nv_bfloat16 g_qs[(size_t)B_ * N_ * 64];   // [b][n][Qh(32)|Ql(32)]  (q pre-scaled by log2e)
__device__ __nv_bfloat16 g_ks[(size_t)B_ * N_ * 64];   // [b][n][Kh|Kl]
__device__ __nv_bfloat16 g_vh[(size_t)B_ * C_ * N_];   // [b][c][n]
__device__ __nv_bfloat16 g_vl[(size_t)B_ * C_ * N_];
__device__ float g_y[(size_t)B_ * C_ * N_];
__device__ float g_mean[C_], g_istd[C_];

// ---------------- PTX helpers (baseline sm_80+ only; no 'a'-gated features) ----------------
__device__ __forceinline__ u32 smem_u32(const void* p) {
    u32 a;
    asm("{ .reg .u64 t; cvta.to.shared.u64 t, %1; cvt.u32.u64 %0, t; }" : "=r"(a) : "l"(p));
    return a;
}
__device__ __forceinline__ void ldsm4(u32* r, u32 a) {
    asm volatile("ldmatrix.sync.aligned.m8n8.x4.shared.b16 {%0,%1,%2,%3}, [%4];"
        : "=r"(r[0]), "=r"(r[1]), "=r"(r[2]), "=r"(r[3]) : "r"(a));
}
__device__ __forceinline__ void mma_bf16(float* d, const u32* a, const u32* b) {
    asm volatile("mma.sync.aligned.m16n8k16.row.col.f32.bf16.bf16.f32 "
        "{%0,%1,%2,%3}, {%4,%5,%6,%7}, {%8,%9}, {%0,%1,%2,%3};"
        : "+f"(d[0]), "+f"(d[1]), "+f"(d[2]), "+f"(d[3])
        : "r"(a[0]), "r"(a[1]), "r"(a[2]), "r"(a[3]), "r"(b[0]), "r"(b[1]));
}
__device__ __forceinline__ void cpa16(u32 d, const void* s) {
    asm volatile("cp.async.cg.shared.global [%0], [%1], 16;" :: "r"(d), "l"(s));
}
#define CP_COMMIT() asm volatile("cp.async.commit_group;" ::: "memory")
#define CP_WAIT0()  asm volatile("cp.async.wait_group 0;" ::: "memory")
__device__ __forceinline__ float ex2f(float a) {
    float d; asm("ex2.approx.f32 %0, %1;" : "=f"(d) : "f"(a)); return d;
}
__device__ __forceinline__ u32 cvt2bf(float hi, float lo) {   // d = {hi:lo}
    u32 d; asm("cvt.rn.bf16x2.f32 %0, %1, %2;" : "=r"(d) : "f"(hi), "f"(lo)); return d;
}
#define BARP(id) asm volatile("bar.sync %0, 64;" :: "r"(id) : "memory")

// ---------------- f32x2 helpers ----------------
__device__ __forceinline__ ull pack2(float v) { ull r; asm("mov.b64 %0, {%1, %1};" : "=l"(r) : "f"(v)); return r; }
__device__ __forceinline__ ull packpair(float a, float b) { ull r; asm("mov.b64 %0, {%1, %2};" : "=l"(r) : "f"(a), "f"(b)); return r; }
__device__ __forceinline__ void ffma2(ull& d, ull a, ull b) { asm("fma.rn.f32x2 %0, %1, %2, %0;" : "+l"(d) : "l"(a), "l"(b)); }
__device__ __forceinline__ float2 unpack2(ull v) { float2 r; asm("mov.b64 {%0, %1}, %2;" : "=f"(r.x), "=f"(r.y) : "l"(v)); return r; }

// ---------------- Q/K projection -> split-bf16 [b][n][hi|lo] ----------------
template<int SEL>
__global__ __launch_bounds__(256) void proj_qk_kernel(const float* __restrict__ x,
                                                      const float* __restrict__ W,
                                                      const float* __restrict__ bias) {
    constexpr int OT = 16;
    __nv_bfloat16* out = SEL ? g_ks : g_qs;
    const float sc = SEL ? 1.0f : 1.4426950408889634f;   // fold log2e into q
    const int n  = blockIdx.x * 1024 + threadIdx.x * 4;
    const int o0 = blockIdx.y * OT;
    const int bb = blockIdx.z;
    __shared__ ull Ws2[OT * 64];
    ull acc[OT][2];
#pragma unroll
    for (int o = 0; o < OT; o++) { acc[o][0] = 0ull; acc[o][1] = 0ull; }
    const float* xb = x + (size_t)bb * C_ * N_;
#pragma unroll 1
    for (int c0 = 0; c0 < C_; c0 += 64) {
        __syncthreads();
        for (int idx = threadIdx.x; idx < OT * 64; idx += 256)
            Ws2[idx] = pack2(W[(o0 + (idx >> 6)) * C_ + c0 + (idx & 63)]);
        __syncthreads();
#pragma unroll 4
        for (int cc = 0; cc < 64; cc++) {
            float4 xv = *(const float4*)&xb[(size_t)(c0 + cc) * N_ + n];
            ull x01 = packpair(xv.x, xv.y), x23 = packpair(xv.z, xv.w);
#pragma unroll
            for (int o = 0; o < OT; o++) {
                ull w2 = Ws2[o * 64 + cc];
                ffma2(acc[o][0], w2, x01);
                ffma2(acc[o][1], w2, x23);
            }
        }
    }
    unsigned short hs[4][OT], ls[4][OT];
#pragma unroll
    for (int o = 0; o < OT; o++) {
        float bo = bias[o0 + o];
        float2 a = unpack2(acc[o][0]), b = unpack2(acc[o][1]);
        float v[4] = {(a.x + bo) * sc, (a.y + bo) * sc, (b.x + bo) * sc, (b.y + bo) * sc};
#pragma unroll
        for (int e = 0; e < 4; e++) {
            __nv_bfloat16 hi = __float2bfloat16(v[e]);
            __nv_bfloat16 lo = __float2bfloat16(v[e] - __bfloat162float(hi));
            hs[e][o] = __bfloat16_as_ushort(hi);
            ls[e][o] = __bfloat16_as_ushort(lo);
        }
    }
    u32* ob = (u32*)out;
#pragma unroll
    for (int e = 0; e < 4; e++) {
        size_t rb = ((size_t)bb * N_ + n + e) * 32;
#pragma unroll
        for (int op = 0; op < 8; op++) {
            ob[rb + (o0 >> 1) + op]      = ((u32)hs[e][2 * op + 1] << 16) | hs[e][2 * op];
            ob[rb + 16 + (o0 >> 1) + op] = ((u32)ls[e][2 * op + 1] << 16) | ls[e][2 * op];
        }
    }
}

// ---------------- V projection -> split-bf16 planes [b][c][n] ----------------
__global__ __launch_bounds__(256) void proj_v_kernel(const float* __restrict__ x,
                                                     const float* __restrict__ W,
                                                     const float* __restrict__ bias) {
    constexpr int OT = 16;
    const int n  = blockIdx.x * 1024 + threadIdx.x * 4;
    const int o0 = blockIdx.y * OT;
    const int bb = blockIdx.z;
    __shared__ ull Ws2[OT * 64];
    ull acc[OT][2];
#pragma unroll
    for (int o = 0; o < OT; o++) { acc[o][0] = 0ull; acc[o][1] = 0ull; }
    const float* xb = x + (size_t)bb * C_ * N_;
#pragma unroll 1
    for (int c0 = 0; c0 < C_; c0 += 64) {
        __syncthreads();
        for (int idx = threadIdx.x; idx < OT * 64; idx += 256)
            Ws2[idx] = pack2(W[(o0 + (idx >> 6)) * C_ + c0 + (idx & 63)]);
        __syncthreads();
#pragma unroll 4
        for (int cc = 0; cc < 64; cc++) {
            float4 xv = *(const float4*)&xb[(size_t)(c0 + cc) * N_ + n];
            ull x01 = packpair(xv.x, xv.y), x23 = packpair(xv.z, xv.w);
#pragma unroll
            for (int o = 0; o < OT; o++) {
                ull w2 = Ws2[o * 64 + cc];
                ffma2(acc[o][0], w2, x01);
                ffma2(acc[o][1], w2, x23);
            }
        }
    }
#pragma unroll
    for (int o = 0; o < OT; o++) {
        float bo = bias[o0 + o];
        float2 a = unpack2(acc[o][0]), b = unpack2(acc[o][1]);
        float v[4] = {a.x + bo, a.y + bo, b.x + bo, b.y + bo};
        unsigned short hv[4], lv[4];
#pragma unroll
        for (int e = 0; e < 4; e++) {
            __nv_bfloat16 hi = __float2bfloat16(v[e]);
            __nv_bfloat16 lo = __float2bfloat16(v[e] - __bfloat162float(hi));
            hv[e] = __bfloat16_as_ushort(hi);
            lv[e] = __bfloat16_as_ushort(lo);
        }
        size_t base = ((size_t)bb * C_ + o0 + o) * N_ + n;
        uint2 uh, ul;
        uh.x = ((u32)hv[1] << 16) | hv[0]; uh.y = ((u32)hv[3] << 16) | hv[2];
        ul.x = ((u32)lv[1] << 16) | lv[0]; ul.y = ((u32)lv[3] << 16) | lv[2];
        *(uint2*)&g_vh[base] = uh;
        *(uint2*)&g_vl[base] = ul;
    }
}

// ---------------- HMMA flash attention, QK deduped by key-split ----------------
// CTA: 64 q x 128 ch, 8 warps. warp (rg = w&3, kh = w>>2):
//   QK phase: rows rg*16..+15, keys kh*32..+31  (no duplication)
//   PV phase: rows rg*16..+15, ch half kh*64..+63 (P via smem/ldmatrix)
constexpr int KOFF  = 9216;                   // Q: [0, 9216)
constexpr int VOFF  = KOFF + 9216;            // K single stage: [9216, 18432)
constexpr int VSTG  = 36864;                  // per stage: hi 128x144 + lo 128x144
constexpr int PHOFF = VOFF + 2 * VSTG;        // 92160
constexpr int PLOFF = PHOFF + 9216;           // 101376
constexpr int PMOFF = PLOFF + 9216;           // 110592 (2 x 64 floats)
constexpr int LSOFF = PMOFF + 512;            // 111104 (2 x 64 floats)
constexpr int SMEM_AT = LSOFF + 512;          // 111616

__global__ __launch_bounds__(256, 2) void attn_kernel(const float* __restrict__ x,
                                                      const float* __restrict__ gamma) {
    extern __shared__ char smc[];
    const u32 sb = smem_u32(smc);
    const int t = threadIdx.x, w = t >> 5, lid = t & 31;
    const int rg = w & 3, kh = w >> 2;
    const int g = lid >> 2, qt = lid & 3;
    const int rw = lid & 7, mi = lid >> 3;
    const int n0 = blockIdx.x * 64, chb = blockIdx.y * 128, bb = blockIdx.z;

    const __nv_bfloat16* qg  = g_qs + (size_t)bb * N_ * 64;
    const __nv_bfloat16* kgm = g_ks + (size_t)bb * N_ * 64;
    const __nv_bfloat16* vhb = g_vh + ((size_t)bb * C_ + chb) * N_;
    const __nv_bfloat16* vlb = g_vl + ((size_t)bb * C_ + chb) * N_;

    // Q -> smem (plain LDG/STS)
#pragma unroll
    for (int p = 0; p < 2; p++) {
        int ck = t + p * 256; int row = ck >> 3, col = ck & 7;
        *(uint4*)(smc + row * 144 + col * 16) = *(const uint4*)(qg + (size_t)(n0 + row) * 64 + col * 8);
    }
    // prefetch K(0), V(0)
    {
#pragma unroll
        for (int p = 0; p < 2; p++) {
            int ck = t + p * 256; int row = ck >> 3, col = ck & 7;
            cpa16(sb + KOFF + row * 144 + col * 16, kgm + (size_t)row * 64 + col * 8);
        }
        CP_COMMIT();
#pragma unroll
        for (int p = 0; p < 4; p++) {
            int cv = t + p * 256; int cr = cv >> 3, col = cv & 7;
            u32 doff = cr * 144 + col * 16;
            cpa16(sb + VOFF + doff,         vhb + (size_t)cr * N_ + col * 8);
            cpa16(sb + VOFF + 18432 + doff, vlb + (size_t)cr * N_ + col * 8);
        }
        CP_COMMIT();
    }
    __syncthreads();

    // Q fragments resident: hi (dims 0-31) and lo (dims 0-31)
    u32 QA[16];
    {
        u32 qa = sb + (u32)(rg * 16 + (mi & 1) * 8 + rw) * 144 + (u32)(mi >> 1) * 16;
        ldsm4(QA + 0,  qa);
        ldsm4(QA + 4,  qa + 32);
        ldsm4(QA + 8,  qa + 64);
        ldsm4(QA + 12, qa + 96);
    }
    float O[32];
#pragma unroll
    for (int i = 0; i < 32; i++) O[i] = 0.f;
    float m0 = -1e30f, m1 = -1e30f, l0 = 0.f, l1 = 0.f;

    float* pmf = (float*)(smc + PMOFF);
    float* lsf = (float*)(smc + LSOFF);

#pragma unroll 1
    for (int kt = 0; kt < NT; kt++) {
        CP_WAIT0();
        __syncthreads();                               // B1: K(kt),V(kt) visible; prev PV done
        // prefetch V(kt+1) into alternate stage
        if (kt + 1 < NT) {
            const int j0 = (kt + 1) * JT;
            u32 sv = sb + VOFF + ((kt + 1) & 1) * VSTG;
#pragma unroll
            for (int p = 0; p < 4; p++) {
                int cv = t + p * 256; int cr = cv >> 3, col = cv & 7;
                u32 doff = cr * 144 + col * 16;
                cpa16(sv + doff,         vhb + (size_t)cr * N_ + j0 + col * 8);
                cpa16(sv + 18432 + doff, vlb + (size_t)cr * N_ + j0 + col * 8);
            }
            CP_COMMIT();
        }

        // ---- QK: own 16 rows x 32-key half (24 MMA)
        float S[16];
#pragma unroll
        for (int i = 0; i < 16; i++) S[i] = 0.f;
        {
            u32 kbase = sb + KOFF + (u32)(kh * 32 + rw) * 144 + (u32)mi * 16;
#pragma unroll
            for (int nt = 0; nt < 4; nt++) {
                u32 kbh[4], kbl[4];
                ldsm4(kbh, kbase + nt * 1152);
                ldsm4(kbl, kbase + nt * 1152 + 64);
                float* S4 = S + nt * 4;
                mma_bf16(S4, QA + 0,  kbh + 0);
                mma_bf16(S4, QA + 4,  kbh + 2);
                mma_bf16(S4, QA + 0,  kbl + 0);
                mma_bf16(S4, QA + 4,  kbl + 2);
                mma_bf16(S4, QA + 8,  kbh + 0);
                mma_bf16(S4, QA + 12, kbh + 2);
            }
        }
        // partial rowmax over this 32-key half
        float tm0 = fmaxf(fmaxf(S[0], S[1]), fmaxf(S[4], S[5]));
        float tm1 = fmaxf(fmaxf(S[2], S[3]), fmaxf(S[6], S[7]));
        tm0 = fmaxf(tm0, fmaxf(fmaxf(S[8], S[9]),  fmaxf(S[12], S[13])));
        tm1 = fmaxf(tm1, fmaxf(fmaxf(S[10], S[11]), fmaxf(S[14], S[15])));
        tm0 = fmaxf(tm0, __shfl_xor_sync(0xffffffffu, tm0, 1));
        tm0 = fmaxf(tm0, __shfl_xor_sync(0xffffffffu, tm0, 2));
        tm1 = fmaxf(tm1, __shfl_xor_sync(0xffffffffu, tm1, 1));
        tm1 = fmaxf(tm1, __shfl_xor_sync(0xffffffffu, tm1, 2));
        if (qt == 0) {
            pmf[kh * 64 + rg * 16 + g]     = tm0;
            pmf[kh * 64 + rg * 16 + g + 8] = tm1;
        }
        __syncthreads();                               // B2: all QK K-reads done, pm ready
        // prefetch K(kt+1) (single K buffer, safe after B2)
        if (kt + 1 < NT) {
            const int j0 = (kt + 1) * JT;
#pragma unroll
            for (int p = 0; p < 2; p++) {
                int ck = t + p * 256; int row = ck >> 3, col = ck & 7;
                cpa16(sb + KOFF + row * 144 + col * 16, kgm + (size_t)(j0 + row) * 64 + col * 8);
            }
            CP_COMMIT();
        }

        // ---- softmax (base-2; q pre-scaled by log2e)
        float mx0 = fmaxf(pmf[rg * 16 + g],     pmf[64 + rg * 16 + g]);
        float mx1 = fmaxf(pmf[rg * 16 + g + 8], pmf[64 + rg * 16 + g + 8]);
        float mn0 = fmaxf(m0, mx0), mn1 = fmaxf(m1, mx1);
        if (mn0 != m0 || mn1 != m1) {
            float a0 = ex2f(m0 - mn0), a1 = ex2f(m1 - mn1);
            l0 *= a0; l1 *= a1;
#pragma unroll
            for (int nt = 0; nt < 8; nt++) {
                O[4 * nt]     *= a0; O[4 * nt + 1] *= a0;
                O[4 * nt + 2] *= a1; O[4 * nt + 3] *= a1;
            }
            m0 = mn0; m1 = mn1;
        }
        {
            const u32 ph_b = (u32)(rg * 16 + g) * 144 + (u32)(kh * 64 + qt * 4);
#pragma unroll
            for (int nt = 0; nt < 4; nt++) {
                float e00 = ex2f(S[4 * nt]     - mn0);
                float e01 = ex2f(S[4 * nt + 1] - mn0);
                float e10 = ex2f(S[4 * nt + 2] - mn1);
                float e11 = ex2f(S[4 * nt + 3] - mn1);
                l0 += e00 + e01; l1 += e10 + e11;
                u32 h0 = cvt2bf(e01, e00);
                u32 h1 = cvt2bf(e11, e10);
                float hl00 = __uint_as_float(h0 << 16),  hl01 = __uint_as_float(h0 & 0xFFFF0000u);
                float hl10 = __uint_as_float(h1 << 16),  hl11 = __uint_as_float(h1 & 0xFFFF0000u);
                u32 lo0 = cvt2bf(e01 - hl01, e00 - hl00);
                u32 lo1 = cvt2bf(e11 - hl11, e10 - hl10);
                *(u32*)(smc + PHOFF + ph_b + nt * 16)             = h0;
                *(u32*)(smc + PHOFF + ph_b + 8 * 144 + nt * 16)   = h1;
                *(u32*)(smc + PLOFF + ph_b + nt * 16)             = lo0;
                *(u32*)(smc + PLOFF + ph_b + 8 * 144 + nt * 16)   = lo1;
            }
        }
        BARP(rg + 1);                                  // B3: pair (rg,0)+(rg,1) — P rows ready

        // ---- PV: rows rg*16, ch half kh*64 (96 MMA)
        {
            const u32 sv = sb + VOFF + (kt & 1) * VSTG;
            u32 pAh = sb + PHOFF + (u32)(rg * 16 + (mi & 1) * 8 + rw) * 144 + (u32)(mi >> 1) * 16;
            u32 pAl = pAh + (PLOFF - PHOFF);
            u32 vb0 = sv + (u32)(kh * 64 + (mi >> 1) * 8 + rw) * 144 + (u32)(mi & 1) * 16;
#pragma unroll
            for (int c = 0; c < 4; c++) {
                u32 ph[4], pl[4];
                ldsm4(ph, pAh + c * 32);
                ldsm4(pl, pAl + c * 32);
#pragma unroll
                for (int a = 0; a < 4; a++) {
                    u32 vh4[4], vl4[4];
                    ldsm4(vh4, vb0 + a * 2304 + c * 32);
                    ldsm4(vl4, vb0 + 18432 + a * 2304 + c * 32);
                    float* Oa = O + a * 8;
                    mma_bf16(Oa,     ph, vh4 + 0);
                    mma_bf16(Oa,     ph, vl4 + 0);
                    mma_bf16(Oa,     pl, vh4 + 0);
                    mma_bf16(Oa + 4, ph, vh4 + 2);
                    mma_bf16(Oa + 4, ph, vl4 + 2);
                    mma_bf16(Oa + 4, pl, vh4 + 2);
                }
            }
        }
    }

    // ---- reduce l across quad (THE R8 BUG: this was missing), merge halves, write out
    l0 += __shfl_xor_sync(0xffffffffu, l0, 1);
    l0 += __shfl_xor_sync(0xffffffffu, l0, 2);
    l1 += __shfl_xor_sync(0xffffffffu, l1, 1);
    l1 += __shfl_xor_sync(0xffffffffu, l1, 2);
    if (qt == 0) {
        lsf[kh * 64 + rg * 16 + g]     = l0;
        lsf[kh * 64 + rg * 16 + g + 8] = l1;
    }
    __syncthreads();
    const float gm = gamma[0];
    const float li0 = gm / (lsf[rg * 16 + g]     + lsf[64 + rg * 16 + g]);
    const float li1 = gm / (lsf[rg * 16 + g + 8] + lsf[64 + rg * 16 + g + 8]);
    float* Os = (float*)(smc + VOFF);   // [128 ch][68] staging
    const int r0 = rg * 16;
#pragma unroll
    for (int nt = 0; nt < 8; nt++) {
        int cw = kh * 64 + nt * 8 + 2 * qt;
        Os[cw * 68 + r0 + g]           = O[4 * nt]     * li0;
        Os[(cw + 1) * 68 + r0 + g]     = O[4 * nt + 1] * li0;
        Os[cw * 68 + r0 + g + 8]       = O[4 * nt + 2] * li1;
        Os[(cw + 1) * 68 + r0 + g + 8] = O[4 * nt + 3] * li1;
    }
    __syncthreads();
    {
        const int ch = t >> 1, q0 = (t & 1) * 32;
        const float* orow = Os + ch * 68 + q0;
        const float* xr = x   + ((size_t)bb * C_ + chb + ch) * N_ + n0 + q0;
        float*       yr = g_y + ((size_t)bb * C_ + chb + ch) * N_ + n0 + q0;
#pragma unroll
        for (int i = 0; i < 32; i += 4) {
            float4 ov = *(const float4*)(orow + i);
            float4 xv = *(const float4*)(xr + i);
            float4 yv;
            yv.x = ov.x + xv.x; yv.y = ov.y + xv.y;
            yv.z = ov.z + xv.z; yv.w = ov.w + xv.w;
            *(float4*)(yr + i) = yv;
        }
    }
}

// ---------------- BatchNorm ----------------
__global__ __launch_bounds__(256) void bn_stats_kernel() {
    const int c = blockIdx.x, t = threadIdx.x;
    float s = 0.f, sq = 0.f;
    for (int idx = t; idx < B_ * N_; idx += 256) {
        float v = g_y[(size_t)(idx >> 12) * C_ * N_ + (size_t)c * N_ + (idx & (N_ - 1))];
        s += v; sq += v * v;
    }
#pragma unroll
    for (int off = 16; off > 0; off >>= 1) {
        s  += __shfl_down_sync(0xffffffffu, s, off);
        sq += __shfl_down_sync(0xffffffffu, sq, off);
    }
    __shared__ float rs[8], rq[8];
    if ((t & 31) == 0) { rs[t >> 5] = s; rq[t >> 5] = sq; }
    __syncthreads();
    if (t < 32) {
        s  = (t < 8) ? rs[t] : 0.f;
        sq = (t < 8) ? rq[t] : 0.f;
#pragma unroll
        for (int off = 4; off > 0; off >>= 1) {
            s  += __shfl_down_sync(0xffffffffu, s, off);
            sq += __shfl_down_sync(0xffffffffu, sq, off);
        }
        if (t == 0) {
            const float inv = 1.0f / (float)(B_ * N_);
            float mean = s * inv;
            float var  = sq * inv - mean * mean;
            g_mean[c] = mean;
            g_istd[c] = rsqrtf(var + 1e-5f);
        }
    }
}

__global__ __launch_bounds__(256) void bn_apply_kernel(const float* __restrict__ bnw,
                                                       const float* __restrict__ bnb,
                                                       float* __restrict__ out) {
    size_t idx = ((size_t)blockIdx.x * 256 + threadIdx.x) * 4;
    int c = (int)((idx >> 12) & (C_ - 1));
    float4 v = *(const float4*)&g_y[idx];
    float is = g_istd[c];
    float wv = bnw[c] * is;
    float bv = bnb[c] - g_mean[c] * wv;
    v.x = fmaxf(fmaf(v.x, wv, bv), 0.f);
    v.y = fmaxf(fmaf(v.y, wv, bv), 0.f);
    v.z = fmaxf(fmaf(v.z, wv, bv), 0.f);
    v.w = fmaxf(fmaf(v.w, wv, bv), 0.f);
    *(float4*)&out[idx] = v;
}

// ---------------- launch ----------------
extern "C" void kernel_launch(void* const* d_in, const int* in_sizes, int n_in,
                              void* d_out, int out_size) {
    const float* x     = (const float*)d_in[0];
    const float* wq    = (const float*)d_in[1];
    const float* bq    = (const float*)d_in[2];
    const float* wk    = (const float*)d_in[3];
    const float* bk    = (const float*)d_in[4];
    const float* wv    = (const float*)d_in[5];
    const float* bv    = (const float*)d_in[6];
    const float* gamma = (const float*)d_in[7];
    const float* bnw   = (const float*)d_in[8];
    const float* bnb   = (const float*)d_in[9];
    float* out = (float*)d_out;

    proj_qk_kernel<0><<<dim3(N_ / 1024, 2, B_), 256>>>(x, wq, bq);
    proj_qk_kernel<1><<<dim3(N_ / 1024, 2, B_), 256>>>(x, wk, bk);
    proj_v_kernel<<<dim3(N_ / 1024, C_ / 16, B_), 256>>>(x, wv, bv);

    cudaFuncSetAttribute(attn_kernel, cudaFuncAttributeMaxDynamicSharedMemorySize, SMEM_AT);
    attn_kernel<<<dim3(N_ / 64, 2, B_), 256, SMEM_AT>>>(x, gamma);

    bn_stats_kernel<<<C_, 256>>>();
    bn_apply_kernel<<<(B_ * C_ * N_) / (256 * 4), 256>>>(bnw, bnb, out);
}

// round 12
// speedup vs baseline: 6.9694x; 1.4559x over previous
#include <cuda_runtime.h>
#include <cuda_fp16.h>

#define B_   8
#define C_   256
#define N_   4096
#define JT   64
#define NT   (N_ / JT)

typedef unsigned int u32;
typedef unsigned long long ull;

// ---------------- scratch (static device globals; no allocations) ----------------
__device__ __half g_qs[(size_t)B_ * N_ * 64];   // [b][n][Qh(32)|Ql(32)]  (q pre-scaled by log2e)
__device__ __half g_ks[(size_t)B_ * N_ * 64];   // [b][n][Kh|Kl]
__device__ __half g_v[(size_t)B_ * C_ * N_];    // [b][c][n]  (fp16, single plane)
__device__ float g_y[(size_t)B_ * C_ * N_];
__device__ float g_mean[C_], g_istd[C_];

// ---------------- PTX helpers (baseline sm_80+ only) ----------------
__device__ __forceinline__ u32 smem_u32(const void* p) {
    u32 a;
    asm("{ .reg .u64 t; cvta.to.shared.u64 t, %1; cvt.u32.u64 %0, t; }" : "=r"(a) : "l"(p));
    return a;
}
__device__ __forceinline__ void ldsm4(u32* r, u32 a) {
    asm volatile("ldmatrix.sync.aligned.m8n8.x4.shared.b16 {%0,%1,%2,%3}, [%4];"
        : "=r"(r[0]), "=r"(r[1]), "=r"(r[2]), "=r"(r[3]) : "r"(a));
}
__device__ __forceinline__ void mma_f16(float* d, const u32* a, const u32* b) {
    asm volatile("mma.sync.aligned.m16n8k16.row.col.f32.f16.f16.f32 "
        "{%0,%1,%2,%3}, {%4,%5,%6,%7}, {%8,%9}, {%0,%1,%2,%3};"
        : "+f"(d[0]), "+f"(d[1]), "+f"(d[2]), "+f"(d[3])
        : "r"(a[0]), "r"(a[1]), "r"(a[2]), "r"(a[3]), "r"(b[0]), "r"(b[1]));
}
__device__ __forceinline__ void cpa16(u32 d, const void* s) {
    asm volatile("cp.async.cg.shared.global [%0], [%1], 16;" :: "r"(d), "l"(s));
}
#define CP_COMMIT() asm volatile("cp.async.commit_group;" ::: "memory")
#define CP_WAIT0()  asm volatile("cp.async.wait_group 0;" ::: "memory")
__device__ __forceinline__ float ex2f(float a) {
    float d; asm("ex2.approx.f32 %0, %1;" : "=f"(d) : "f"(a)); return d;
}
__device__ __forceinline__ u32 cvt2h(float hi, float lo) {   // d = {hi:lo} packed f16x2
    u32 d; asm("cvt.rn.f16x2.f32 %0, %1, %2;" : "=r"(d) : "f"(hi), "f"(lo)); return d;
}
#define BARP(id) asm volatile("bar.sync %0, 64;" :: "r"(id) : "memory")

// ---------------- f32x2 helpers ----------------
__device__ __forceinline__ ull pack2(float v) { ull r; asm("mov.b64 %0, {%1, %1};" : "=l"(r) : "f"(v)); return r; }
__device__ __forceinline__ ull packpair(float a, float b) { ull r; asm("mov.b64 %0, {%1, %2};" : "=l"(r) : "f"(a), "f"(b)); return r; }
__device__ __forceinline__ void ffma2(ull& d, ull a, ull b) { asm("fma.rn.f32x2 %0, %1, %2, %0;" : "+l"(d) : "l"(a), "l"(b)); }
__device__ __forceinline__ float2 unpack2(ull v) { float2 r; asm("mov.b64 {%0, %1}, %2;" : "=f"(r.x), "=f"(r.y) : "l"(v)); return r; }

// ---------------- Q/K projection -> split-fp16 [b][n][hi|lo] ----------------
template<int SEL>
__global__ __launch_bounds__(256) void proj_qk_kernel(const float* __restrict__ x,
                                                      const float* __restrict__ W,
                                                      const float* __restrict__ bias) {
    constexpr int OT = 16;
    __half* out = SEL ? g_ks : g_qs;
    const float sc = SEL ? 1.0f : 1.4426950408889634f;   // fold log2e into q
    const int n  = blockIdx.x * 1024 + threadIdx.x * 4;
    const int o0 = blockIdx.y * OT;
    const int bb = blockIdx.z;
    __shared__ ull Ws2[OT * 64];
    ull acc[OT][2];
#pragma unroll
    for (int o = 0; o < OT; o++) { acc[o][0] = 0ull; acc[o][1] = 0ull; }
    const float* xb = x + (size_t)bb * C_ * N_;
#pragma unroll 1
    for (int c0 = 0; c0 < C_; c0 += 64) {
        __syncthreads();
        for (int idx = threadIdx.x; idx < OT * 64; idx += 256)
            Ws2[idx] = pack2(W[(o0 + (idx >> 6)) * C_ + c0 + (idx & 63)]);
        __syncthreads();
#pragma unroll 4
        for (int cc = 0; cc < 64; cc++) {
            float4 xv = *(const float4*)&xb[(size_t)(c0 + cc) * N_ + n];
            ull x01 = packpair(xv.x, xv.y), x23 = packpair(xv.z, xv.w);
#pragma unroll
            for (int o = 0; o < OT; o++) {
                ull w2 = Ws2[o * 64 + cc];
                ffma2(acc[o][0], w2, x01);
                ffma2(acc[o][1], w2, x23);
            }
        }
    }
    unsigned short hs[4][OT], ls[4][OT];
#pragma unroll
    for (int o = 0; o < OT; o++) {
        float bo = bias[o0 + o];
        float2 a = unpack2(acc[o][0]), b = unpack2(acc[o][1]);
        float v[4] = {(a.x + bo) * sc, (a.y + bo) * sc, (b.x + bo) * sc, (b.y + bo) * sc};
#pragma unroll
        for (int e = 0; e < 4; e++) {
            __half hi = __float2half_rn(v[e]);
            __half lo = __float2half_rn(v[e] - __half2float(hi));
            hs[e][o] = __half_as_ushort(hi);
            ls[e][o] = __half_as_ushort(lo);
        }
    }
    u32* ob = (u32*)out;
#pragma unroll
    for (int e = 0; e < 4; e++) {
        size_t rb = ((size_t)bb * N_ + n + e) * 32;
#pragma unroll
        for (int op = 0; op < 8; op++) {
            ob[rb + (o0 >> 1) + op]      = ((u32)hs[e][2 * op + 1] << 16) | hs[e][2 * op];
            ob[rb + 16 + (o0 >> 1) + op] = ((u32)ls[e][2 * op + 1] << 16) | ls[e][2 * op];
        }
    }
}

// ---------------- V projection -> fp16 plane [b][c][n] ----------------
__global__ __launch_bounds__(256) void proj_v_kernel(const float* __restrict__ x,
                                                     const float* __restrict__ W,
                                                     const float* __restrict__ bias) {
    constexpr int OT = 16;
    const int n  = blockIdx.x * 1024 + threadIdx.x * 4;
    const int o0 = blockIdx.y * OT;
    const int bb = blockIdx.z;
    __shared__ ull Ws2[OT * 64];
    ull acc[OT][2];
#pragma unroll
    for (int o = 0; o < OT; o++) { acc[o][0] = 0ull; acc[o][1] = 0ull; }
    const float* xb = x + (size_t)bb * C_ * N_;
#pragma unroll 1
    for (int c0 = 0; c0 < C_; c0 += 64) {
        __syncthreads();
        for (int idx = threadIdx.x; idx < OT * 64; idx += 256)
            Ws2[idx] = pack2(W[(o0 + (idx >> 6)) * C_ + c0 + (idx & 63)]);
        __syncthreads();
#pragma unroll 4
        for (int cc = 0; cc < 64; cc++) {
            float4 xv = *(const float4*)&xb[(size_t)(c0 + cc) * N_ + n];
            ull x01 = packpair(xv.x, xv.y), x23 = packpair(xv.z, xv.w);
#pragma unroll
            for (int o = 0; o < OT; o++) {
                ull w2 = Ws2[o * 64 + cc];
                ffma2(acc[o][0], w2, x01);
                ffma2(acc[o][1], w2, x23);
            }
        }
    }
#pragma unroll
    for (int o = 0; o < OT; o++) {
        float bo = bias[o0 + o];
        float2 a = unpack2(acc[o][0]), b = unpack2(acc[o][1]);
        uint2 uh;
        uh.x = cvt2h(a.y + bo, a.x + bo);
        uh.y = cvt2h(b.y + bo, b.x + bo);
        *(uint2*)&g_v[((size_t)bb * C_ + o0 + o) * N_ + n] = uh;
    }
}

// ---------------- HMMA fp16 flash attention, QK key-split dedup ----------------
// CTA: 64 q x 128 ch, 8 warps. warp (rg = w&3, kh = w>>2):
//   QK: rows rg*16..+15, keys kh*32..+31 (split-fp16, 3 products, 24 MMA)
//   PV: rows rg*16..+15, ch half kh*64..+63 (fp16 direct, 32 MMA)
constexpr int KOFF  = 9216;                   // Q: [0, 9216)
constexpr int VOFF  = KOFF + 9216;            // K single stage: [9216, 18432)
constexpr int VSTG  = 18432;                  // V stage: 128 ch x 144B (fp16, single plane)
constexpr int PHOFF = VOFF + 2 * VSTG;        // 55296
constexpr int PMOFF = PHOFF + 9216;           // 64512 (2 x 64 floats)
constexpr int LSOFF = PMOFF + 512;            // 65024
constexpr int SMEM_AT = LSOFF + 512;          // 65536

__global__ __launch_bounds__(256, 2) void attn_kernel(const float* __restrict__ x,
                                                      const float* __restrict__ gamma) {
    extern __shared__ char smc[];
    const u32 sb = smem_u32(smc);
    const int t = threadIdx.x, w = t >> 5, lid = t & 31;
    const int rg = w & 3, kh = w >> 2;
    const int g = lid >> 2, qt = lid & 3;
    const int rw = lid & 7, mi = lid >> 3;
    const int n0 = blockIdx.x * 64, chb = blockIdx.y * 128, bb = blockIdx.z;

    const __half* qg  = g_qs + (size_t)bb * N_ * 64;
    const __half* kgm = g_ks + (size_t)bb * N_ * 64;
    const __half* vb  = g_v  + ((size_t)bb * C_ + chb) * N_;

    // Q -> smem
#pragma unroll
    for (int p = 0; p < 2; p++) {
        int ck = t + p * 256; int row = ck >> 3, col = ck & 7;
        *(uint4*)(smc + row * 144 + col * 16) = *(const uint4*)(qg + (size_t)(n0 + row) * 64 + col * 8);
    }
    // prefetch K(0), V(0)
    {
#pragma unroll
        for (int p = 0; p < 2; p++) {
            int ck = t + p * 256; int row = ck >> 3, col = ck & 7;
            cpa16(sb + KOFF + row * 144 + col * 16, kgm + (size_t)row * 64 + col * 8);
        }
        CP_COMMIT();
#pragma unroll
        for (int p = 0; p < 4; p++) {
            int cv = t + p * 256; int cr = cv >> 3, col = cv & 7;
            cpa16(sb + VOFF + cr * 144 + col * 16, vb + (size_t)cr * N_ + col * 8);
        }
        CP_COMMIT();
    }
    __syncthreads();

    // Q fragments resident: hi (dims 0-31), lo (dims 0-31)
    u32 QA[16];
    {
        u32 qa = sb + (u32)(rg * 16 + (mi & 1) * 8 + rw) * 144 + (u32)(mi >> 1) * 16;
        ldsm4(QA + 0,  qa);
        ldsm4(QA + 4,  qa + 32);
        ldsm4(QA + 8,  qa + 64);
        ldsm4(QA + 12, qa + 96);
    }
    float O[32];
#pragma unroll
    for (int i = 0; i < 32; i++) O[i] = 0.f;
    float m0 = -1e30f, m1 = -1e30f, l0 = 0.f, l1 = 0.f;

    float* pmf = (float*)(smc + PMOFF);
    float* lsf = (float*)(smc + LSOFF);

#pragma unroll 1
    for (int kt = 0; kt < NT; kt++) {
        CP_WAIT0();
        __syncthreads();                               // B1: K(kt),V(kt) visible; prev PV done
        // prefetch V(kt+1)
        if (kt + 1 < NT) {
            const int j0 = (kt + 1) * JT;
            u32 sv = sb + VOFF + ((kt + 1) & 1) * VSTG;
#pragma unroll
            for (int p = 0; p < 4; p++) {
                int cv = t + p * 256; int cr = cv >> 3, col = cv & 7;
                cpa16(sv + cr * 144 + col * 16, vb + (size_t)cr * N_ + j0 + col * 8);
            }
            CP_COMMIT();
        }

        // ---- QK: 16 rows x 32-key half, 3 split products (24 MMA)
        float S[16];
#pragma unroll
        for (int i = 0; i < 16; i++) S[i] = 0.f;
        {
            u32 kbase = sb + KOFF + (u32)(kh * 32 + rw) * 144 + (u32)mi * 16;
#pragma unroll
            for (int nt = 0; nt < 4; nt++) {
                u32 kbh[4], kbl[4];
                ldsm4(kbh, kbase + nt * 1152);
                ldsm4(kbl, kbase + nt * 1152 + 64);
                float* S4 = S + nt * 4;
                mma_f16(S4, QA + 0,  kbh + 0);
                mma_f16(S4, QA + 4,  kbh + 2);
                mma_f16(S4, QA + 0,  kbl + 0);
                mma_f16(S4, QA + 4,  kbl + 2);
                mma_f16(S4, QA + 8,  kbh + 0);
                mma_f16(S4, QA + 12, kbh + 2);
            }
        }
        // partial rowmax over this 32-key half
        float tm0 = fmaxf(fmaxf(S[0], S[1]), fmaxf(S[4], S[5]));
        float tm1 = fmaxf(fmaxf(S[2], S[3]), fmaxf(S[6], S[7]));
        tm0 = fmaxf(tm0, fmaxf(fmaxf(S[8], S[9]),  fmaxf(S[12], S[13])));
        tm1 = fmaxf(tm1, fmaxf(fmaxf(S[10], S[11]), fmaxf(S[14], S[15])));
        tm0 = fmaxf(tm0, __shfl_xor_sync(0xffffffffu, tm0, 1));
        tm0 = fmaxf(tm0, __shfl_xor_sync(0xffffffffu, tm0, 2));
        tm1 = fmaxf(tm1, __shfl_xor_sync(0xffffffffu, tm1, 1));
        tm1 = fmaxf(tm1, __shfl_xor_sync(0xffffffffu, tm1, 2));
        if (qt == 0) {
            pmf[kh * 64 + rg * 16 + g]     = tm0;
            pmf[kh * 64 + rg * 16 + g + 8] = tm1;
        }
        __syncthreads();                               // B2: QK K-reads done, pm ready
        // prefetch K(kt+1) (single K buffer)
        if (kt + 1 < NT) {
            const int j0 = (kt + 1) * JT;
#pragma unroll
            for (int p = 0; p < 2; p++) {
                int ck = t + p * 256; int row = ck >> 3, col = ck & 7;
                cpa16(sb + KOFF + row * 144 + col * 16, kgm + (size_t)(j0 + row) * 64 + col * 8);
            }
            CP_COMMIT();
        }

        // ---- softmax (base-2; q pre-scaled by log2e); P -> fp16 smem
        float mx0 = fmaxf(pmf[rg * 16 + g],     pmf[64 + rg * 16 + g]);
        float mx1 = fmaxf(pmf[rg * 16 + g + 8], pmf[64 + rg * 16 + g + 8]);
        float mn0 = fmaxf(m0, mx0), mn1 = fmaxf(m1, mx1);
        if (mn0 != m0 || mn1 != m1) {
            float a0 = ex2f(m0 - mn0), a1 = ex2f(m1 - mn1);
            l0 *= a0; l1 *= a1;
#pragma unroll
            for (int nt = 0; nt < 8; nt++) {
                O[4 * nt]     *= a0; O[4 * nt + 1] *= a0;
                O[4 * nt + 2] *= a1; O[4 * nt + 3] *= a1;
            }
            m0 = mn0; m1 = mn1;
        }
        {
            const u32 ph_b = (u32)(rg * 16 + g) * 144 + (u32)(kh * 64 + qt * 4);
#pragma unroll
            for (int nt = 0; nt < 4; nt++) {
                float e00 = ex2f(S[4 * nt]     - mn0);
                float e01 = ex2f(S[4 * nt + 1] - mn0);
                float e10 = ex2f(S[4 * nt + 2] - mn1);
                float e11 = ex2f(S[4 * nt + 3] - mn1);
                l0 += e00 + e01; l1 += e10 + e11;
                *(u32*)(smc + PHOFF + ph_b + nt * 16)           = cvt2h(e01, e00);
                *(u32*)(smc + PHOFF + ph_b + 8 * 144 + nt * 16) = cvt2h(e11, e10);
            }
        }
        BARP(rg + 1);                                  // B3: pair (rg,0)+(rg,1) — P rows ready

        // ---- PV: rows rg*16, ch half kh*64 (32 MMA, fp16 direct)
        {
            const u32 sv = sb + VOFF + (kt & 1) * VSTG;
            u32 pAh = sb + PHOFF + (u32)(rg * 16 + (mi & 1) * 8 + rw) * 144 + (u32)(mi >> 1) * 16;
            u32 vb0 = sv + (u32)(kh * 64 + (mi >> 1) * 8 + rw) * 144 + (u32)(mi & 1) * 16;
#pragma unroll
            for (int c = 0; c < 4; c++) {
                u32 ph[4];
                ldsm4(ph, pAh + c * 32);
#pragma unroll
                for (int a = 0; a < 4; a++) {
                    u32 v4[4];
                    ldsm4(v4, vb0 + a * 2304 + c * 32);
                    float* Oa = O + a * 8;
                    mma_f16(Oa,     ph, v4 + 0);
                    mma_f16(Oa + 4, ph, v4 + 2);
                }
            }
        }
    }

    // ---- reduce l across quad, merge halves, write out
    l0 += __shfl_xor_sync(0xffffffffu, l0, 1);
    l0 += __shfl_xor_sync(0xffffffffu, l0, 2);
    l1 += __shfl_xor_sync(0xffffffffu, l1, 1);
    l1 += __shfl_xor_sync(0xffffffffu, l1, 2);
    if (qt == 0) {
        lsf[kh * 64 + rg * 16 + g]     = l0;
        lsf[kh * 64 + rg * 16 + g + 8] = l1;
    }
    __syncthreads();
    const float gm = gamma[0];
    const float li0 = gm / (lsf[rg * 16 + g]     + lsf[64 + rg * 16 + g]);
    const float li1 = gm / (lsf[rg * 16 + g + 8] + lsf[64 + rg * 16 + g + 8]);
    float* Os = (float*)(smc + VOFF);   // [128 ch][68] staging (34816 <= 36864)
    const int r0 = rg * 16;
#pragma unroll
    for (int nt = 0; nt < 8; nt++) {
        int cw = kh * 64 + nt * 8 + 2 * qt;
        Os[cw * 68 + r0 + g]           = O[4 * nt]     * li0;
        Os[(cw + 1) * 68 + r0 + g]     = O[4 * nt + 1] * li0;
        Os[cw * 68 + r0 + g + 8]       = O[4 * nt + 2] * li1;
        Os[(cw + 1) * 68 + r0 + g + 8] = O[4 * nt + 3] * li1;
    }
    __syncthreads();
    {
        const int ch = t >> 1, q0 = (t & 1) * 32;
        const float* orow = Os + ch * 68 + q0;
        const float* xr = x   + ((size_t)bb * C_ + chb + ch) * N_ + n0 + q0;
        float*       yr = g_y + ((size_t)bb * C_ + chb + ch) * N_ + n0 + q0;
#pragma unroll
        for (int i = 0; i < 32; i += 4) {
            float4 ov = *(const float4*)(orow + i);
            float4 xv = *(const float4*)(xr + i);
            float4 yv;
            yv.x = ov.x + xv.x; yv.y = ov.y + xv.y;
            yv.z = ov.z + xv.z; yv.w = ov.w + xv.w;
            *(float4*)(yr + i) = yv;
        }
    }
}

// ---------------- BatchNorm ----------------
__global__ __launch_bounds__(256) void bn_stats_kernel() {
    const int c = blockIdx.x, t = threadIdx.x;
    float s = 0.f, sq = 0.f;
    for (int idx = t; idx < B_ * N_; idx += 256) {
        float v = g_y[(size_t)(idx >> 12) * C_ * N_ + (size_t)c * N_ + (idx & (N_ - 1))];
        s += v; sq += v * v;
    }
#pragma unroll
    for (int off = 16; off > 0; off >>= 1) {
        s  += __shfl_down_sync(0xffffffffu, s, off);
        sq += __shfl_down_sync(0xffffffffu, sq, off);
    }
    __shared__ float rs[8], rq[8];
    if ((t & 31) == 0) { rs[t >> 5] = s; rq[t >> 5] = sq; }
    __syncthreads();
    if (t < 32) {
        s  = (t < 8) ? rs[t] : 0.f;
        sq = (t < 8) ? rq[t] : 0.f;
#pragma unroll
        for (int off = 4; off > 0; off >>= 1) {
            s  += __shfl_down_sync(0xffffffffu, s, off);
            sq += __shfl_down_sync(0xffffffffu, sq, off);
        }
        if (t == 0) {
            const float inv = 1.0f / (float)(B_ * N_);
            float mean = s * inv;
            float var  = sq * inv - mean * mean;
            g_mean[c] = mean;
            g_istd[c] = rsqrtf(var + 1e-5f);
        }
    }
}

__global__ __launch_bounds__(256) void bn_apply_kernel(const float* __restrict__ bnw,
                                                       const float* __restrict__ bnb,
                                                       float* __restrict__ out) {
    size_t idx = ((size_t)blockIdx.x * 256 + threadIdx.x) * 4;
    int c = (int)((idx >> 12) & (C_ - 1));
    float4 v = *(const float4*)&g_y[idx];
    float is = g_istd[c];
    float wv = bnw[c] * is;
    float bv = bnb[c] - g_mean[c] * wv;
    v.x = fmaxf(fmaf(v.x, wv, bv), 0.f);
    v.y = fmaxf(fmaf(v.y, wv, bv), 0.f);
    v.z = fmaxf(fmaf(v.z, wv, bv), 0.f);
    v.w = fmaxf(fmaf(v.w, wv, bv), 0.f);
    *(float4*)&out[idx] = v;
}

// ---------------- launch ----------------
extern "C" void kernel_launch(void* const* d_in, const int* in_sizes, int n_in,
                              void* d_out, int out_size) {
    const float* x     = (const float*)d_in[0];
    const float* wq    = (const float*)d_in[1];
    const float* bq    = (const float*)d_in[2];
    const float* wk    = (const float*)d_in[3];
    const float* bk    = (const float*)d_in[4];
    const float* wv    = (const float*)d_in[5];
    const float* bv    = (const float*)d_in[6];
    const float* gamma = (const float*)d_in[7];
    const float* bnw   = (const float*)d_in[8];
    const float* bnb   = (const float*)d_in[9];
    float* out = (float*)d_out;

    proj_qk_kernel<0><<<dim3(N_ / 1024, 2, B_), 256>>>(x, wq, bq);
    proj_qk_kernel<1><<<dim3(N_ / 1024, 2, B_), 256>>>(x, wk, bk);
    proj_v_kernel<<<dim3(N_ / 1024, C_ / 16, B_), 256>>>(x, wv, bv);

    cudaFuncSetAttribute(attn_kernel, cudaFuncAttributeMaxDynamicSharedMemorySize, SMEM_AT);
    attn_kernel<<<dim3(N_ / 64, 2, B_), 256, SMEM_AT>>>(x, gamma);

    bn_stats_kernel<<<C_, 256>>>();
    bn_apply_kernel<<<(B_ * C_ * N_) / (256 * 4), 256>>>(bnw, bnb, out);
}